// round 2
// baseline (speedup 1.0000x reference)
#include <cuda_runtime.h>

#define B_ 8
#define S_ 2048
#define E_ 512

// Scratch (allocation-free rule: __device__ globals). 3x32MB + 128MB = 224MB.
__device__ float g_q[(size_t)B_ * S_ * E_];
__device__ float g_k[(size_t)B_ * S_ * E_];
__device__ float g_v[(size_t)B_ * S_ * E_];
__device__ float g_p[(size_t)B_ * S_ * S_];

// ---------------------------------------------------------------------------
// NT SGEMM: C[M,N] = scale * (A[M,K] . B[N,K]^T), optional +bias[col],
// optional mask epilogue (mask>0 -> -1e30). 128x128x8 tile, 256 threads,
// 8x8 per thread (classic 4+4 split). Batched via blockIdx.z + strides.
// All dims assumed multiples of the tile (true for this problem).
// ---------------------------------------------------------------------------
template <bool ADD_BIAS, bool DO_MASK>
__global__ __launch_bounds__(256, 2)
void gemm_nt_kernel(const float* __restrict__ A, const float* __restrict__ Bmat,
                    const float* __restrict__ bias, const int* __restrict__ mask,
                    float* __restrict__ C, int K, int N,
                    long strideA, long strideB, long strideC, float scale)
{
    const int bz = blockIdx.z;
    A    += (long)bz * strideA;
    Bmat += (long)bz * strideB;
    C    += (long)bz * strideC;
    const int bm = blockIdx.y * 128;
    const int bn = blockIdx.x * 128;

    __shared__ float As[8][128];
    __shared__ float Bs[8][128];

    const int tid = threadIdx.x;        // 0..255
    const int tx  = tid & 15;           // 0..15
    const int ty  = tid >> 4;           // 0..15

    // global load mapping: 2 threads per row, float4 each (8 floats/row/tile)
    const int la_row = tid >> 1;        // 0..127
    const int la_col = (tid & 1) * 4;   // 0 or 4
    const float* Aptr = A    + (long)(bm + la_row) * K + la_col;
    const float* Bptr = Bmat + (long)(bn + la_row) * K + la_col;

    float acc[8][8];
#pragma unroll
    for (int i = 0; i < 8; i++)
#pragma unroll
        for (int j = 0; j < 8; j++) acc[i][j] = 0.0f;

    for (int k0 = 0; k0 < K; k0 += 8) {
        const float4 av = *reinterpret_cast<const float4*>(Aptr + k0);
        const float4 bv = *reinterpret_cast<const float4*>(Bptr + k0);
        __syncthreads();   // previous iteration's compute done before overwrite
        As[la_col + 0][la_row] = av.x;
        As[la_col + 1][la_row] = av.y;
        As[la_col + 2][la_row] = av.z;
        As[la_col + 3][la_row] = av.w;
        Bs[la_col + 0][la_row] = bv.x;
        Bs[la_col + 1][la_row] = bv.y;
        Bs[la_col + 2][la_row] = bv.z;
        Bs[la_col + 3][la_row] = bv.w;
        __syncthreads();
#pragma unroll
        for (int k = 0; k < 8; k++) {
            const float4 a0 = *reinterpret_cast<const float4*>(&As[k][ty * 4]);
            const float4 a1 = *reinterpret_cast<const float4*>(&As[k][ty * 4 + 64]);
            const float4 b0 = *reinterpret_cast<const float4*>(&Bs[k][tx * 4]);
            const float4 b1 = *reinterpret_cast<const float4*>(&Bs[k][tx * 4 + 64]);
            const float af[8] = {a0.x, a0.y, a0.z, a0.w, a1.x, a1.y, a1.z, a1.w};
            const float bf[8] = {b0.x, b0.y, b0.z, b0.w, b1.x, b1.y, b1.z, b1.w};
#pragma unroll
            for (int i = 0; i < 8; i++)
#pragma unroll
                for (int j = 0; j < 8; j++) acc[i][j] = fmaf(af[i], bf[j], acc[i][j]);
        }
    }

#pragma unroll
    for (int i = 0; i < 8; i++) {
        const int row = bm + ty * 4 + ((i < 4) ? i : (64 + i - 4));
#pragma unroll
        for (int j = 0; j < 8; j++) {
            const int col = bn + tx * 4 + ((j < 4) ? j : (64 + j - 4));
            float v = acc[i][j] * scale;
            if (ADD_BIAS) v += bias[col];
            if (DO_MASK) {
                // mask shares C's batch stride/leading dim ([S,S] per batch)
                if (mask[(long)bz * strideC + (long)row * N + col] > 0) v = -1e30f;
            }
            C[(long)row * N + col] = v;
        }
    }
}

// ---------------------------------------------------------------------------
// NN SGEMM: C[M,N] = A[M,K] . B[K,N]. Same tiling. Batched via blockIdx.z.
// ---------------------------------------------------------------------------
__global__ __launch_bounds__(256, 2)
void gemm_nn_kernel(const float* __restrict__ A, const float* __restrict__ Bmat,
                    float* __restrict__ C, int K, int N,
                    long strideA, long strideB, long strideC)
{
    const int bz = blockIdx.z;
    A    += (long)bz * strideA;
    Bmat += (long)bz * strideB;
    C    += (long)bz * strideC;
    const int bm = blockIdx.y * 128;
    const int bn = blockIdx.x * 128;

    __shared__ float As[8][128];
    __shared__ float Bs[8][128];

    const int tid = threadIdx.x;
    const int tx  = tid & 15;
    const int ty  = tid >> 4;

    const int la_row = tid >> 1;        // A: K-contiguous rows
    const int la_col = (tid & 1) * 4;
    const float* Aptr = A + (long)(bm + la_row) * K + la_col;

    const int lb_row = tid >> 5;        // B: [K,N], 8 rows x 128 cols
    const int lb_col = (tid & 31) * 4;
    const float* Bptr = Bmat + (long)lb_row * N + (bn + lb_col);

    float acc[8][8];
#pragma unroll
    for (int i = 0; i < 8; i++)
#pragma unroll
        for (int j = 0; j < 8; j++) acc[i][j] = 0.0f;

    for (int k0 = 0; k0 < K; k0 += 8) {
        const float4 av = *reinterpret_cast<const float4*>(Aptr + k0);
        const float4 bv = *reinterpret_cast<const float4*>(Bptr + (long)k0 * N);
        __syncthreads();
        As[la_col + 0][la_row] = av.x;
        As[la_col + 1][la_row] = av.y;
        As[la_col + 2][la_row] = av.z;
        As[la_col + 3][la_row] = av.w;
        *reinterpret_cast<float4*>(&Bs[lb_row][lb_col]) = bv;
        __syncthreads();
#pragma unroll
        for (int k = 0; k < 8; k++) {
            const float4 a0 = *reinterpret_cast<const float4*>(&As[k][ty * 4]);
            const float4 a1 = *reinterpret_cast<const float4*>(&As[k][ty * 4 + 64]);
            const float4 b0 = *reinterpret_cast<const float4*>(&Bs[k][tx * 4]);
            const float4 b1 = *reinterpret_cast<const float4*>(&Bs[k][tx * 4 + 64]);
            const float af[8] = {a0.x, a0.y, a0.z, a0.w, a1.x, a1.y, a1.z, a1.w};
            const float bf[8] = {b0.x, b0.y, b0.z, b0.w, b1.x, b1.y, b1.z, b1.w};
#pragma unroll
            for (int i = 0; i < 8; i++)
#pragma unroll
                for (int j = 0; j < 8; j++) acc[i][j] = fmaf(af[i], bf[j], acc[i][j]);
        }
    }

#pragma unroll
    for (int i = 0; i < 8; i++) {
        const int row = bm + ty * 4 + ((i < 4) ? i : (64 + i - 4));
#pragma unroll
        for (int j = 0; j < 8; j++) {
            const int col = bn + tx * 4 + ((j < 4) ? j : (64 + j - 4));
            C[(long)row * N + col] = acc[i][j];
        }
    }
}

// ---------------------------------------------------------------------------
// Row softmax over length-2048 rows of g_p, in place. One block per row.
// ---------------------------------------------------------------------------
__global__ __launch_bounds__(256)
void softmax_kernel(float* __restrict__ P)
{
    float* p = P + (long)blockIdx.x * S_;
    const int tid = threadIdx.x;
    __shared__ float red[256];

    float lmax = -1e30f;
    for (int i = tid; i < S_; i += 256) lmax = fmaxf(lmax, p[i]);
    red[tid] = lmax;
    __syncthreads();
#pragma unroll
    for (int s = 128; s > 0; s >>= 1) {
        if (tid < s) red[tid] = fmaxf(red[tid], red[tid + s]);
        __syncthreads();
    }
    const float m = red[0];
    __syncthreads();

    float lsum = 0.0f;
    for (int i = tid; i < S_; i += 256) {
        const float e = __expf(p[i] - m);
        p[i] = e;
        lsum += e;
    }
    red[tid] = lsum;
    __syncthreads();
#pragma unroll
    for (int s = 128; s > 0; s >>= 1) {
        if (tid < s) red[tid] += red[tid + s];
        __syncthreads();
    }
    const float inv = 1.0f / red[0];

    for (int i = tid; i < S_; i += 256) p[i] *= inv;
}

// ---------------------------------------------------------------------------
extern "C" void kernel_launch(void* const* d_in, const int* in_sizes, int n_in,
                              void* d_out, int out_size)
{
    const float* x    = (const float*)d_in[0];
    const int*   mask = (const int*)  d_in[1];
    const float* wq   = (const float*)d_in[2];
    const float* bq   = (const float*)d_in[3];
    const float* wk   = (const float*)d_in[4];
    const float* bk   = (const float*)d_in[5];
    const float* wv   = (const float*)d_in[6];
    const float* bv   = (const float*)d_in[7];
    float* out = (float*)d_out;

    float *gq, *gk, *gv, *gp;
    cudaGetSymbolAddress((void**)&gq, g_q);
    cudaGetSymbolAddress((void**)&gk, g_k);
    cudaGetSymbolAddress((void**)&gv, g_v);
    cudaGetSymbolAddress((void**)&gp, g_p);

    const dim3 blk(256);

    // 1) QKV projections: [16384,512] = x[16384,512] . W[512,512]^T + b
    const dim3 grid_qkv(E_ / 128, (B_ * S_) / 128, 1);
    gemm_nt_kernel<true, false><<<grid_qkv, blk>>>(x, wq, bq, nullptr, gq, E_, E_, 0, 0, 0, 1.0f);
    gemm_nt_kernel<true, false><<<grid_qkv, blk>>>(x, wk, bk, nullptr, gk, E_, E_, 0, 0, 0, 1.0f);
    gemm_nt_kernel<true, false><<<grid_qkv, blk>>>(x, wv, bv, nullptr, gv, E_, E_, 0, 0, 0, 1.0f);

    // 2) scores = scale * Q.K^T with mask -> -1e30 fused
    const float scale = 0.044194173824159216f;  // 1/sqrt(512)
    const dim3 grid_sc(S_ / 128, S_ / 128, B_);
    gemm_nt_kernel<false, true><<<grid_sc, blk>>>(gq, gk, nullptr, mask, gp, E_, S_,
                                                  (long)S_ * E_, (long)S_ * E_,
                                                  (long)S_ * S_, scale);

    // 3) row softmax in place
    softmax_kernel<<<B_ * S_, 256>>>(gp);

    // 4) out = P . V
    const dim3 grid_out(E_ / 128, S_ / 128, B_);
    gemm_nn_kernel<<<grid_out, blk>>>(gp, gv, out, S_, E_,
                                      (long)S_ * S_, (long)S_ * E_, (long)S_ * E_);
}

// round 4
// speedup vs baseline: 1.8710x; 1.8710x over previous
#include <cuda_runtime.h>
#include <cuda_fp16.h>
#include <cstdint>

#define B_ 8
#define S_ 2048
#define E_ 512

// ---------------- scratch (__device__ globals; no allocs allowed) ----------
__device__ __align__(16) float g_q[(size_t)B_ * S_ * E_];
__device__ __align__(16) float g_k[(size_t)B_ * S_ * E_];
__device__ __align__(16) float g_v[(size_t)B_ * S_ * E_];
__device__ __align__(16) float g_p[(size_t)B_ * S_ * S_];

__device__ __align__(16) __half g_xhi[(size_t)B_ * S_ * E_];
__device__ __align__(16) __half g_xlo[(size_t)B_ * S_ * E_];
__device__ __align__(16) __half g_qhi[(size_t)B_ * S_ * E_];
__device__ __align__(16) __half g_qlo[(size_t)B_ * S_ * E_];
__device__ __align__(16) __half g_khi[(size_t)B_ * S_ * E_];
__device__ __align__(16) __half g_klo[(size_t)B_ * S_ * E_];
__device__ __align__(16) __half g_vthi[(size_t)B_ * E_ * S_];  // [B][E][S]
__device__ __align__(16) __half g_vtlo[(size_t)B_ * E_ * S_];
__device__ __align__(16) __half g_phi[(size_t)B_ * S_ * S_];
__device__ __align__(16) __half g_plo[(size_t)B_ * S_ * S_];
__device__ __align__(16) __half g_wqh[E_ * E_], g_wql[E_ * E_];
__device__ __align__(16) __half g_wkh[E_ * E_], g_wkl[E_ * E_];
__device__ __align__(16) __half g_wvh[E_ * E_], g_wvl[E_ * E_];

// ---------------- helpers ---------------------------------------------------
__device__ __forceinline__ uint32_t smem_u32(const void* p) {
    uint32_t a;
    asm("{ .reg .u64 t; cvta.to.shared.u64 t, %1; cvt.u32.u64 %0, t; }"
        : "=r"(a) : "l"(p));
    return a;
}
__device__ __forceinline__ void cp16(uint32_t dst, const void* src) {
    asm volatile("cp.async.cg.shared.global [%0], [%1], 16;"
                 :: "r"(dst), "l"(src) : "memory");
}
__device__ __forceinline__ void cp_commit() {
    asm volatile("cp.async.commit_group;" ::: "memory");
}
template <int N>
__device__ __forceinline__ void cp_wait() {
    asm volatile("cp.async.wait_group %0;" :: "n"(N) : "memory");
}
__device__ __forceinline__ void ldm_x4(uint32_t& r0, uint32_t& r1, uint32_t& r2,
                                       uint32_t& r3, uint32_t addr) {
    asm volatile("ldmatrix.sync.aligned.m8n8.x4.shared.b16 {%0,%1,%2,%3}, [%4];"
                 : "=r"(r0), "=r"(r1), "=r"(r2), "=r"(r3) : "r"(addr));
}
__device__ __forceinline__ void mma16816(float* d, const uint32_t* a, const uint32_t* b) {
    asm volatile("mma.sync.aligned.m16n8k16.row.col.f32.f16.f16.f32 "
                 "{%0,%1,%2,%3}, {%4,%5,%6,%7}, {%8,%9}, {%0,%1,%2,%3};"
                 : "+f"(d[0]), "+f"(d[1]), "+f"(d[2]), "+f"(d[3])
                 : "r"(a[0]), "r"(a[1]), "r"(a[2]), "r"(a[3]), "r"(b[0]), "r"(b[1]));
}

// ---------------------------------------------------------------------------
// NT GEMM, fp16x3 split emulating fp32:
//   C[M,N] = scale * (A . B^T) (+ epilogue), A=[M,K] hi/lo, B=[N,K] hi/lo.
// Block: 128x128, 8 warps (4m x 2n), warp tile 32x64. KC=32, double-buffered.
// EPI: 0 = +bias ; 1 = *scale + mask>0 -> -1e30 ; 2 = plain
// ---------------------------------------------------------------------------
#define KC 32
#define TSTR 40                       // padded halfs per smem row
#define TILE_B (128 * TSTR * 2)       // 10240 bytes per half-tile
#define STAGE_B (4 * TILE_B)          // AH, AL, BH, BL
#define SMEM_SZ (2 * STAGE_B)         // 81920

template <int EPI>
__global__ void __launch_bounds__(256)
gemm_f16x3(const __half* __restrict__ Ahi, const __half* __restrict__ Alo,
           const __half* __restrict__ Bhi, const __half* __restrict__ Blo,
           const float* __restrict__ bias, const int* __restrict__ mask,
           float* __restrict__ C, int K, int N,
           long sA, long sB, long sC, float scale)
{
    extern __shared__ __align__(16) char sm[];
    const uint32_t sb = smem_u32(sm);

    const int tid  = threadIdx.x;
    const int lane = tid & 31;
    const int wid  = tid >> 5;
    const int warp_m = wid & 3;       // 0..3 -> m offset *32
    const int warp_n = wid >> 2;      // 0..1 -> n offset *64

    const int bz = blockIdx.z;
    Ahi += (long)bz * sA; Alo += (long)bz * sA;
    Bhi += (long)bz * sB; Blo += (long)bz * sB;
    C   += (long)bz * sC;
    if (EPI == 1) mask += (long)bz * sC;
    const int bm = blockIdx.y * 128;
    const int bn = blockIdx.x * 128;

    // ---- global -> smem chunk loader (cp.async) ----
    const int lr  = tid >> 2;          // row 0..63 (two passes -> 128)
    const int ls  = tid & 3;           // 16B segment 0..3
    auto load_chunk = [&](int c) {
        const uint32_t st = sb + (uint32_t)(c & 1) * STAGE_B;
        const int k0 = c * KC;
#pragma unroll
        for (int t = 0; t < 2; ++t) {
            const int r = lr + t * 64;
            const uint32_t so = (uint32_t)(r * (TSTR * 2) + ls * 16);
            const long ga = (long)(bm + r) * K + k0 + ls * 8;
            const long gb = (long)(bn + r) * K + k0 + ls * 8;
            cp16(st + 0 * TILE_B + so, Ahi + ga);
            cp16(st + 1 * TILE_B + so, Alo + ga);
            cp16(st + 2 * TILE_B + so, Bhi + gb);
            cp16(st + 3 * TILE_B + so, Blo + gb);
        }
        cp_commit();
    };

    float acc[2][8][4];
#pragma unroll
    for (int mi = 0; mi < 2; ++mi)
#pragma unroll
        for (int ni = 0; ni < 8; ++ni)
#pragma unroll
            for (int r = 0; r < 4; ++r) acc[mi][ni][r] = 0.0f;

    // per-lane ldmatrix address geometry
    const int quad = lane >> 3, lm8 = lane & 7;
    const int a_row = warp_m * 32 + lm8 + (quad & 1) * 8;   // + mi*16
    const int a_col = (quad >> 1) * 8;                       // + ks
    const int b_row = warp_n * 64 + lm8 + (quad >> 1) * 8;   // + np*16
    const int b_col = (quad & 1) * 8;                        // + ks

    const int nch = K / KC;
    load_chunk(0);
    for (int c = 0; c < nch; ++c) {
        if (c + 1 < nch) { load_chunk(c + 1); cp_wait<1>(); }
        else             { cp_wait<0>(); }
        __syncthreads();

        const uint32_t st = sb + (uint32_t)(c & 1) * STAGE_B;
#pragma unroll
        for (int ks = 0; ks < KC; ks += 16) {
            uint32_t ah[2][4], al[2][4], bh[8][2], bl[8][2];
#pragma unroll
            for (int mi = 0; mi < 2; ++mi) {
                const uint32_t ao =
                    (uint32_t)(((a_row + mi * 16) * TSTR + a_col + ks) * 2);
                ldm_x4(ah[mi][0], ah[mi][1], ah[mi][2], ah[mi][3], st + 0 * TILE_B + ao);
                ldm_x4(al[mi][0], al[mi][1], al[mi][2], al[mi][3], st + 1 * TILE_B + ao);
            }
#pragma unroll
            for (int np = 0; np < 4; ++np) {
                const uint32_t bo =
                    (uint32_t)(((b_row + np * 16) * TSTR + b_col + ks) * 2);
                ldm_x4(bh[2 * np][0], bh[2 * np][1], bh[2 * np + 1][0], bh[2 * np + 1][1],
                       st + 2 * TILE_B + bo);
                ldm_x4(bl[2 * np][0], bl[2 * np][1], bl[2 * np + 1][0], bl[2 * np + 1][1],
                       st + 3 * TILE_B + bo);
            }
#pragma unroll
            for (int mi = 0; mi < 2; ++mi)
#pragma unroll
                for (int ni = 0; ni < 8; ++ni) {
                    mma16816(acc[mi][ni], ah[mi], bh[ni]);
                    mma16816(acc[mi][ni], ah[mi], bl[ni]);
                    mma16816(acc[mi][ni], al[mi], bh[ni]);
                }
        }
        __syncthreads();
    }

    // ---- epilogue ----
#pragma unroll
    for (int mi = 0; mi < 2; ++mi)
#pragma unroll
        for (int ni = 0; ni < 8; ++ni) {
            const int row0 = bm + warp_m * 32 + mi * 16 + (lane >> 2);
            const int col0 = bn + warp_n * 64 + ni * 8 + (lane & 3) * 2;
            float c0 = acc[mi][ni][0], c1 = acc[mi][ni][1];
            float c2 = acc[mi][ni][2], c3 = acc[mi][ni][3];
            if (EPI == 0) {
                const float2 bb = *reinterpret_cast<const float2*>(&bias[col0]);
                c0 += bb.x; c1 += bb.y; c2 += bb.x; c3 += bb.y;
            }
            if (EPI == 1) {
                c0 *= scale; c1 *= scale; c2 *= scale; c3 *= scale;
                const int2 ma = *reinterpret_cast<const int2*>(&mask[(long)row0 * N + col0]);
                const int2 mb = *reinterpret_cast<const int2*>(&mask[(long)(row0 + 8) * N + col0]);
                if (ma.x > 0) c0 = -1e30f;
                if (ma.y > 0) c1 = -1e30f;
                if (mb.x > 0) c2 = -1e30f;
                if (mb.y > 0) c3 = -1e30f;
            }
            *reinterpret_cast<float2*>(&C[(long)row0 * N + col0])       = make_float2(c0, c1);
            *reinterpret_cast<float2*>(&C[(long)(row0 + 8) * N + col0]) = make_float2(c2, c3);
        }
}

// ---------------------------------------------------------------------------
// fp32 -> (hi, lo) fp16 split (float4 granularity)
// ---------------------------------------------------------------------------
__global__ void __launch_bounds__(256)
split_kernel(const float* __restrict__ src, __half* __restrict__ hi,
             __half* __restrict__ lo, long n4)
{
    const long i = (long)blockIdx.x * blockDim.x + threadIdx.x;
    if (i >= n4) return;
    const float4 v = reinterpret_cast<const float4*>(src)[i];
    const __half h0 = __float2half_rn(v.x), h1 = __float2half_rn(v.y);
    const __half h2 = __float2half_rn(v.z), h3 = __float2half_rn(v.w);
    const __half l0 = __float2half_rn(v.x - __half2float(h0));
    const __half l1 = __float2half_rn(v.y - __half2float(h1));
    const __half l2 = __float2half_rn(v.z - __half2float(h2));
    const __half l3 = __float2half_rn(v.w - __half2float(h3));
    __half2* hi2 = reinterpret_cast<__half2*>(hi);
    __half2* lo2 = reinterpret_cast<__half2*>(lo);
    hi2[2 * i]     = __halves2half2(h0, h1);
    hi2[2 * i + 1] = __halves2half2(h2, h3);
    lo2[2 * i]     = __halves2half2(l0, l1);
    lo2[2 * i + 1] = __halves2half2(l2, l3);
}

// ---------------------------------------------------------------------------
// V [B][S][E] fp32 -> Vt hi/lo [B][E][S] fp16 (tiled transpose + split)
// ---------------------------------------------------------------------------
__global__ void __launch_bounds__(256)
transpose_split_kernel(const float* __restrict__ v,
                       __half* __restrict__ th, __half* __restrict__ tl)
{
    __shared__ float t[32][33];
    const int b = blockIdx.z;
    const int e0 = blockIdx.x * 32;
    const int s0 = blockIdx.y * 32;
    const int tx = threadIdx.x, ty = threadIdx.y;  // 32 x 8
#pragma unroll
    for (int j = 0; j < 4; ++j) {
        const int s = s0 + ty + j * 8;
        t[ty + j * 8][tx] = v[((long)b * S_ + s) * E_ + e0 + tx];
    }
    __syncthreads();
#pragma unroll
    for (int j = 0; j < 4; ++j) {
        const int e = e0 + ty + j * 8;
        const float val = t[tx][ty + j * 8];
        const __half h = __float2half_rn(val);
        const __half l = __float2half_rn(val - __half2float(h));
        const long o = ((long)b * E_ + e) * S_ + s0 + tx;
        th[o] = h;
        tl[o] = l;
    }
}

// ---------------------------------------------------------------------------
// Row softmax over fp32 scores; emits P as (hi, lo) fp16.
// ---------------------------------------------------------------------------
__global__ void __launch_bounds__(256)
softmax_split_kernel(const float* __restrict__ P,
                     __half* __restrict__ phi, __half* __restrict__ plo)
{
    const float* p = P + (long)blockIdx.x * S_;
    __half* oh = phi + (long)blockIdx.x * S_;
    __half* ol = plo + (long)blockIdx.x * S_;
    const int tid = threadIdx.x;
    __shared__ float red[256];

    float lmax = -1e30f;
    for (int i = tid; i < S_; i += 256) lmax = fmaxf(lmax, p[i]);
    red[tid] = lmax;
    __syncthreads();
#pragma unroll
    for (int s = 128; s > 0; s >>= 1) {
        if (tid < s) red[tid] = fmaxf(red[tid], red[tid + s]);
        __syncthreads();
    }
    const float m = red[0];
    __syncthreads();

    float lsum = 0.0f;
    float e_cache[8];
#pragma unroll
    for (int j = 0; j < 8; ++j) {
        const float e = __expf(p[tid + j * 256] - m);
        e_cache[j] = e;
        lsum += e;
    }
    red[tid] = lsum;
    __syncthreads();
#pragma unroll
    for (int s = 128; s > 0; s >>= 1) {
        if (tid < s) red[tid] += red[tid + s];
        __syncthreads();
    }
    const float inv = 1.0f / red[0];
#pragma unroll
    for (int j = 0; j < 8; ++j) {
        const float val = e_cache[j] * inv;
        const __half h = __float2half_rn(val);
        const __half l = __float2half_rn(val - __half2float(h));
        oh[tid + j * 256] = h;
        ol[tid + j * 256] = l;
    }
}

// ---------------------------------------------------------------------------
extern "C" void kernel_launch(void* const* d_in, const int* in_sizes, int n_in,
                              void* d_out, int out_size)
{
    const float* x    = (const float*)d_in[0];
    const int*   mask = (const int*)  d_in[1];
    const float* wq   = (const float*)d_in[2];
    const float* bq   = (const float*)d_in[3];
    const float* wk   = (const float*)d_in[4];
    const float* bk   = (const float*)d_in[5];
    const float* wv   = (const float*)d_in[6];
    const float* bv   = (const float*)d_in[7];
    float* out = (float*)d_out;

    float *gq, *gk, *gv, *gp;
    cudaGetSymbolAddress((void**)&gq, g_q);
    cudaGetSymbolAddress((void**)&gk, g_k);
    cudaGetSymbolAddress((void**)&gv, g_v);
    cudaGetSymbolAddress((void**)&gp, g_p);
    __half *xhi, *xlo, *qhi, *qlo, *khi, *klo, *vthi, *vtlo, *phi, *plo;
    __half *wqh, *wql, *wkh, *wkl, *wvh, *wvl;
    cudaGetSymbolAddress((void**)&xhi, g_xhi);   cudaGetSymbolAddress((void**)&xlo, g_xlo);
    cudaGetSymbolAddress((void**)&qhi, g_qhi);   cudaGetSymbolAddress((void**)&qlo, g_qlo);
    cudaGetSymbolAddress((void**)&khi, g_khi);   cudaGetSymbolAddress((void**)&klo, g_klo);
    cudaGetSymbolAddress((void**)&vthi, g_vthi); cudaGetSymbolAddress((void**)&vtlo, g_vtlo);
    cudaGetSymbolAddress((void**)&phi, g_phi);   cudaGetSymbolAddress((void**)&plo, g_plo);
    cudaGetSymbolAddress((void**)&wqh, g_wqh);   cudaGetSymbolAddress((void**)&wql, g_wql);
    cudaGetSymbolAddress((void**)&wkh, g_wkh);   cudaGetSymbolAddress((void**)&wkl, g_wkl);
    cudaGetSymbolAddress((void**)&wvh, g_wvh);   cudaGetSymbolAddress((void**)&wvl, g_wvl);

    cudaFuncSetAttribute(gemm_f16x3<0>, cudaFuncAttributeMaxDynamicSharedMemorySize, SMEM_SZ);
    cudaFuncSetAttribute(gemm_f16x3<1>, cudaFuncAttributeMaxDynamicSharedMemorySize, SMEM_SZ);
    cudaFuncSetAttribute(gemm_f16x3<2>, cudaFuncAttributeMaxDynamicSharedMemorySize, SMEM_SZ);

    const long nx = (long)B_ * S_ * E_;          // 8.4M
    const long nw = (long)E_ * E_;               // 262144

    // 1) splits of x and weights
    split_kernel<<<(unsigned)((nx / 4 + 255) / 256), 256>>>(x, xhi, xlo, nx / 4);
    split_kernel<<<(unsigned)((nw / 4 + 255) / 256), 256>>>(wq, wqh, wql, nw / 4);
    split_kernel<<<(unsigned)((nw / 4 + 255) / 256), 256>>>(wk, wkh, wkl, nw / 4);
    split_kernel<<<(unsigned)((nw / 4 + 255) / 256), 256>>>(wv, wvh, wvl, nw / 4);

    // 2) projections: [16384,512] = x . W^T + b  (fp32 out)
    const dim3 gproj(E_ / 128, (B_ * S_) / 128, 1);
    gemm_f16x3<0><<<gproj, 256, SMEM_SZ>>>(xhi, xlo, wqh, wql, bq, nullptr, gq,
                                           E_, E_, 0, 0, 0, 1.0f);
    gemm_f16x3<0><<<gproj, 256, SMEM_SZ>>>(xhi, xlo, wkh, wkl, bk, nullptr, gk,
                                           E_, E_, 0, 0, 0, 1.0f);
    gemm_f16x3<0><<<gproj, 256, SMEM_SZ>>>(xhi, xlo, wvh, wvl, bv, nullptr, gv,
                                           E_, E_, 0, 0, 0, 1.0f);

    // 3) split Q, K ; transpose+split V
    split_kernel<<<(unsigned)((nx / 4 + 255) / 256), 256>>>(gq, qhi, qlo, nx / 4);
    split_kernel<<<(unsigned)((nx / 4 + 255) / 256), 256>>>(gk, khi, klo, nx / 4);
    transpose_split_kernel<<<dim3(E_ / 32, S_ / 32, B_), dim3(32, 8)>>>(gv, vthi, vtlo);

    // 4) scores = scale * Q.K^T, mask -> -1e30, fp32 out
    const float scale = 0.044194173824159216f;  // 512^-0.5
    const dim3 gsc(S_ / 128, S_ / 128, B_);
    gemm_f16x3<1><<<gsc, 256, SMEM_SZ>>>(qhi, qlo, khi, klo, nullptr, mask, gp,
                                         E_, S_, (long)S_ * E_, (long)S_ * E_,
                                         (long)S_ * S_, scale);

    // 5) softmax -> P (hi, lo)
    softmax_split_kernel<<<B_ * S_, 256>>>(gp, phi, plo);

    // 6) out = P . V  (= P . Vt^T), fp32 out
    const dim3 gpv(E_ / 128, S_ / 128, B_);
    gemm_f16x3<2><<<gpv, 256, SMEM_SZ>>>(phi, plo, vthi, vtlo, nullptr, nullptr, out,
                                         S_, E_, (long)S_ * S_, (long)E_ * S_,
                                         (long)S_ * E_, 1.0f);
}

// round 5
// speedup vs baseline: 2.5532x; 1.3646x over previous
#include <cuda_runtime.h>
#include <cuda_fp16.h>
#include <cstdint>

#define B_ 8
#define S_ 2048
#define E_ 512

// ---------------- scratch (__device__ globals; no allocs allowed) ----------
__device__ __align__(16) float g_v[(size_t)B_ * S_ * E_];
__device__ __align__(16) float g_p[(size_t)B_ * S_ * S_];

__device__ __align__(16) __half g_xhi[(size_t)B_ * S_ * E_];
__device__ __align__(16) __half g_xlo[(size_t)B_ * S_ * E_];
__device__ __align__(16) __half g_qhi[(size_t)B_ * S_ * E_];
__device__ __align__(16) __half g_khi[(size_t)B_ * S_ * E_];
__device__ __align__(16) __half g_klo[(size_t)B_ * S_ * E_];
__device__ __align__(16) __half g_vthi[(size_t)B_ * E_ * S_];  // [B][E][S]
__device__ __align__(16) __half g_vtlo[(size_t)B_ * E_ * S_];
__device__ __align__(16) __half g_phi[(size_t)B_ * S_ * S_];
__device__ __align__(16) __half g_wqh[E_ * E_], g_wql[E_ * E_];
__device__ __align__(16) __half g_wkh[E_ * E_], g_wkl[E_ * E_];
__device__ __align__(16) __half g_wvh[E_ * E_], g_wvl[E_ * E_];

// ---------------- helpers ---------------------------------------------------
__device__ __forceinline__ uint32_t smem_u32(const void* p) {
    uint32_t a;
    asm("{ .reg .u64 t; cvta.to.shared.u64 t, %1; cvt.u32.u64 %0, t; }"
        : "=r"(a) : "l"(p));
    return a;
}
__device__ __forceinline__ void cp16(uint32_t dst, const void* src) {
    asm volatile("cp.async.cg.shared.global [%0], [%1], 16;"
                 :: "r"(dst), "l"(src) : "memory");
}
__device__ __forceinline__ void cp_commit() {
    asm volatile("cp.async.commit_group;" ::: "memory");
}
template <int N>
__device__ __forceinline__ void cp_wait() {
    asm volatile("cp.async.wait_group %0;" :: "n"(N) : "memory");
}
__device__ __forceinline__ void ldm_x4(uint32_t& r0, uint32_t& r1, uint32_t& r2,
                                       uint32_t& r3, uint32_t addr) {
    asm volatile("ldmatrix.sync.aligned.m8n8.x4.shared.b16 {%0,%1,%2,%3}, [%4];"
                 : "=r"(r0), "=r"(r1), "=r"(r2), "=r"(r3) : "r"(addr));
}
__device__ __forceinline__ void mma16816(float* d, const uint32_t* a, const uint32_t* b) {
    asm volatile("mma.sync.aligned.m16n8k16.row.col.f32.f16.f16.f32 "
                 "{%0,%1,%2,%3}, {%4,%5,%6,%7}, {%8,%9}, {%0,%1,%2,%3};"
                 : "+f"(d[0]), "+f"(d[1]), "+f"(d[2]), "+f"(d[3])
                 : "r"(a[0]), "r"(a[1]), "r"(a[2]), "r"(a[3]), "r"(b[0]), "r"(b[1]));
}

// ---------------------------------------------------------------------------
// NT GEMM via fp16 split MMAs:
//   C = scale * (A . B^T) (+ epilogue).  A=[M,K] (hi[,lo]), B=[N,K] (hi[,lo]).
// MMA terms: AhBh (+AhBl if BLO) (+AlBh if ALO).
// Block 128x128, 8 warps (4m x 2n), warp tile 32x64, KC=32, double-buffered.
// EPI: 0 = +bias -> fp32 C
//      1 = *scale, mask>0 -> -1e30 -> fp32 C
//      2 = plain fp32 C
//      3 = +bias -> half outH + half outL
//      4 = +bias -> half outH only
// ---------------------------------------------------------------------------
#define KC 32
#define TSTR 40                        // padded halfs per smem row
#define TILE_B (128 * TSTR * 2)        // 10240 bytes per tile

template <int EPI, bool ALO, bool BLO>
__global__ void __launch_bounds__(256)
gemm_f16s(const __half* __restrict__ Ahi, const __half* __restrict__ Alo,
          const __half* __restrict__ Bhi, const __half* __restrict__ Blo,
          const float* __restrict__ bias, const int* __restrict__ mask,
          float* __restrict__ C, __half* __restrict__ outH, __half* __restrict__ outL,
          int K, int N, long sA, long sB, long sC, float scale)
{
    constexpr uint32_t oAH = 0;
    constexpr uint32_t oAL = TILE_B;                              // valid iff ALO
    constexpr uint32_t oBH = (ALO ? 2u : 1u) * TILE_B;
    constexpr uint32_t oBL = oBH + TILE_B;                        // valid iff BLO
    constexpr uint32_t STAGE_B = (2u + (ALO ? 1u : 0u) + (BLO ? 1u : 0u)) * TILE_B;

    extern __shared__ __align__(16) char sm[];
    const uint32_t sb = smem_u32(sm);

    const int tid  = threadIdx.x;
    const int lane = tid & 31;
    const int wid  = tid >> 5;
    const int warp_m = wid & 3;
    const int warp_n = wid >> 2;

    const int bz = blockIdx.z;
    Ahi += (long)bz * sA;
    if (ALO) Alo += (long)bz * sA;
    Bhi += (long)bz * sB;
    if (BLO) Blo += (long)bz * sB;
    if (EPI == 1) mask += (long)bz * sC;
    if (EPI == 0 || EPI == 1 || EPI == 2) C += (long)bz * sC;
    if (EPI == 3 || EPI == 4) outH += (long)bz * sC;
    if (EPI == 3) outL += (long)bz * sC;
    const int bm = blockIdx.y * 128;
    const int bn = blockIdx.x * 128;

    const int lr = tid >> 2;           // row 0..63 (two passes -> 128)
    const int ls = tid & 3;            // 16B segment
    auto load_chunk = [&](int c) {
        const uint32_t st = sb + (uint32_t)(c & 1) * STAGE_B;
        const int k0 = c * KC;
#pragma unroll
        for (int t = 0; t < 2; ++t) {
            const int r = lr + t * 64;
            const uint32_t so = (uint32_t)(r * (TSTR * 2) + ls * 16);
            const long ga = (long)(bm + r) * K + k0 + ls * 8;
            const long gb = (long)(bn + r) * K + k0 + ls * 8;
            cp16(st + oAH + so, Ahi + ga);
            if (ALO) cp16(st + oAL + so, Alo + ga);
            cp16(st + oBH + so, Bhi + gb);
            if (BLO) cp16(st + oBL + so, Blo + gb);
        }
        cp_commit();
    };

    float acc[2][8][4];
#pragma unroll
    for (int mi = 0; mi < 2; ++mi)
#pragma unroll
        for (int ni = 0; ni < 8; ++ni)
#pragma unroll
            for (int r = 0; r < 4; ++r) acc[mi][ni][r] = 0.0f;

    const int quad = lane >> 3, lm8 = lane & 7;
    const int a_row = warp_m * 32 + lm8 + (quad & 1) * 8;
    const int a_col = (quad >> 1) * 8;
    const int b_row = warp_n * 64 + lm8 + (quad >> 1) * 8;
    const int b_col = (quad & 1) * 8;

    const int nch = K / KC;
    load_chunk(0);
    for (int c = 0; c < nch; ++c) {
        if (c + 1 < nch) { load_chunk(c + 1); cp_wait<1>(); }
        else             { cp_wait<0>(); }
        __syncthreads();

        const uint32_t st = sb + (uint32_t)(c & 1) * STAGE_B;
#pragma unroll
        for (int ks = 0; ks < KC; ks += 16) {
            uint32_t ah[2][4], al[2][4], bh[8][2], bl[8][2];
#pragma unroll
            for (int mi = 0; mi < 2; ++mi) {
                const uint32_t ao =
                    (uint32_t)(((a_row + mi * 16) * TSTR + a_col + ks) * 2);
                ldm_x4(ah[mi][0], ah[mi][1], ah[mi][2], ah[mi][3], st + oAH + ao);
                if (ALO)
                    ldm_x4(al[mi][0], al[mi][1], al[mi][2], al[mi][3], st + oAL + ao);
            }
#pragma unroll
            for (int np = 0; np < 4; ++np) {
                const uint32_t bo =
                    (uint32_t)(((b_row + np * 16) * TSTR + b_col + ks) * 2);
                ldm_x4(bh[2 * np][0], bh[2 * np][1], bh[2 * np + 1][0], bh[2 * np + 1][1],
                       st + oBH + bo);
                if (BLO)
                    ldm_x4(bl[2 * np][0], bl[2 * np][1], bl[2 * np + 1][0], bl[2 * np + 1][1],
                           st + oBL + bo);
            }
#pragma unroll
            for (int mi = 0; mi < 2; ++mi)
#pragma unroll
                for (int ni = 0; ni < 8; ++ni) {
                    mma16816(acc[mi][ni], ah[mi], bh[ni]);
                    if (BLO) mma16816(acc[mi][ni], ah[mi], bl[ni]);
                    if (ALO) mma16816(acc[mi][ni], al[mi], bh[ni]);
                }
        }
        __syncthreads();
    }

    // ---- epilogue ----
#pragma unroll
    for (int mi = 0; mi < 2; ++mi)
#pragma unroll
        for (int ni = 0; ni < 8; ++ni) {
            const int row0 = bm + warp_m * 32 + mi * 16 + (lane >> 2);
            const int col0 = bn + warp_n * 64 + ni * 8 + (lane & 3) * 2;
            float c0 = acc[mi][ni][0], c1 = acc[mi][ni][1];
            float c2 = acc[mi][ni][2], c3 = acc[mi][ni][3];
            if (EPI == 0 || EPI == 3 || EPI == 4) {
                const float2 bb = *reinterpret_cast<const float2*>(&bias[col0]);
                c0 += bb.x; c1 += bb.y; c2 += bb.x; c3 += bb.y;
            }
            if (EPI == 1) {
                c0 *= scale; c1 *= scale; c2 *= scale; c3 *= scale;
                const int2 ma = *reinterpret_cast<const int2*>(&mask[(long)row0 * N + col0]);
                const int2 mb = *reinterpret_cast<const int2*>(&mask[(long)(row0 + 8) * N + col0]);
                if (ma.x > 0) c0 = -1e30f;
                if (ma.y > 0) c1 = -1e30f;
                if (mb.x > 0) c2 = -1e30f;
                if (mb.y > 0) c3 = -1e30f;
            }
            if (EPI == 3 || EPI == 4) {
                const __half h0 = __float2half_rn(c0), h1 = __float2half_rn(c1);
                const __half h2 = __float2half_rn(c2), h3 = __float2half_rn(c3);
                *reinterpret_cast<__half2*>(&outH[(long)row0 * N + col0]) =
                    __halves2half2(h0, h1);
                *reinterpret_cast<__half2*>(&outH[(long)(row0 + 8) * N + col0]) =
                    __halves2half2(h2, h3);
                if (EPI == 3) {
                    const __half l0 = __float2half_rn(c0 - __half2float(h0));
                    const __half l1 = __float2half_rn(c1 - __half2float(h1));
                    const __half l2 = __float2half_rn(c2 - __half2float(h2));
                    const __half l3 = __float2half_rn(c3 - __half2float(h3));
                    *reinterpret_cast<__half2*>(&outL[(long)row0 * N + col0]) =
                        __halves2half2(l0, l1);
                    *reinterpret_cast<__half2*>(&outL[(long)(row0 + 8) * N + col0]) =
                        __halves2half2(l2, l3);
                }
            } else {
                *reinterpret_cast<float2*>(&C[(long)row0 * N + col0]) = make_float2(c0, c1);
                *reinterpret_cast<float2*>(&C[(long)(row0 + 8) * N + col0]) = make_float2(c2, c3);
            }
        }
}

// ---------------------------------------------------------------------------
// fp32 -> (hi, lo) fp16 split (float4 granularity)
// ---------------------------------------------------------------------------
__global__ void __launch_bounds__(256)
split_kernel(const float* __restrict__ src, __half* __restrict__ hi,
             __half* __restrict__ lo, long n4)
{
    const long i = (long)blockIdx.x * blockDim.x + threadIdx.x;
    if (i >= n4) return;
    const float4 v = reinterpret_cast<const float4*>(src)[i];
    const __half h0 = __float2half_rn(v.x), h1 = __float2half_rn(v.y);
    const __half h2 = __float2half_rn(v.z), h3 = __float2half_rn(v.w);
    const __half l0 = __float2half_rn(v.x - __half2float(h0));
    const __half l1 = __float2half_rn(v.y - __half2float(h1));
    const __half l2 = __float2half_rn(v.z - __half2float(h2));
    const __half l3 = __float2half_rn(v.w - __half2float(h3));
    __half2* hi2 = reinterpret_cast<__half2*>(hi);
    __half2* lo2 = reinterpret_cast<__half2*>(lo);
    hi2[2 * i]     = __halves2half2(h0, h1);
    hi2[2 * i + 1] = __halves2half2(h2, h3);
    lo2[2 * i]     = __halves2half2(l0, l1);
    lo2[2 * i + 1] = __halves2half2(l2, l3);
}

// ---------------------------------------------------------------------------
// V [B][S][E] fp32 -> Vt hi/lo [B][E][S] fp16 (tiled transpose + split)
// ---------------------------------------------------------------------------
__global__ void __launch_bounds__(256)
transpose_split_kernel(const float* __restrict__ v,
                       __half* __restrict__ th, __half* __restrict__ tl)
{
    __shared__ float t[32][33];
    const int b = blockIdx.z;
    const int e0 = blockIdx.x * 32;
    const int s0 = blockIdx.y * 32;
    const int tx = threadIdx.x, ty = threadIdx.y;  // 32 x 8
#pragma unroll
    for (int j = 0; j < 4; ++j) {
        const int s = s0 + ty + j * 8;
        t[ty + j * 8][tx] = v[((long)b * S_ + s) * E_ + e0 + tx];
    }
    __syncthreads();
#pragma unroll
    for (int j = 0; j < 4; ++j) {
        const int e = e0 + ty + j * 8;
        const float val = t[tx][ty + j * 8];
        const __half h = __float2half_rn(val);
        const __half l = __float2half_rn(val - __half2float(h));
        const long o = ((long)b * E_ + e) * S_ + s0 + tx;
        th[o] = h;
        tl[o] = l;
    }
}

// ---------------------------------------------------------------------------
// Row softmax over fp32 scores; emits P hi (fp16) only.
// ---------------------------------------------------------------------------
__global__ void __launch_bounds__(256)
softmax_kernel(const float* __restrict__ P, __half* __restrict__ phi)
{
    const float* p = P + (long)blockIdx.x * S_;
    __half* oh = phi + (long)blockIdx.x * S_;
    const int tid = threadIdx.x;
    __shared__ float red[256];

    float lmax = -1e30f;
    for (int i = tid; i < S_; i += 256) lmax = fmaxf(lmax, p[i]);
    red[tid] = lmax;
    __syncthreads();
#pragma unroll
    for (int s = 128; s > 0; s >>= 1) {
        if (tid < s) red[tid] = fmaxf(red[tid], red[tid + s]);
        __syncthreads();
    }
    const float m = red[0];
    __syncthreads();

    float lsum = 0.0f;
    float e_cache[8];
#pragma unroll
    for (int j = 0; j < 8; ++j) {
        const float e = __expf(p[tid + j * 256] - m);
        e_cache[j] = e;
        lsum += e;
    }
    red[tid] = lsum;
    __syncthreads();
#pragma unroll
    for (int s = 128; s > 0; s >>= 1) {
        if (tid < s) red[tid] += red[tid + s];
        __syncthreads();
    }
    const float inv = 1.0f / red[0];
#pragma unroll
    for (int j = 0; j < 8; ++j)
        oh[tid + j * 256] = __float2half_rn(e_cache[j] * inv);
}

// ---------------------------------------------------------------------------
extern "C" void kernel_launch(void* const* d_in, const int* in_sizes, int n_in,
                              void* d_out, int out_size)
{
    const float* x    = (const float*)d_in[0];
    const int*   mask = (const int*)  d_in[1];
    const float* wq   = (const float*)d_in[2];
    const float* bq   = (const float*)d_in[3];
    const float* wk   = (const float*)d_in[4];
    const float* bk   = (const float*)d_in[5];
    const float* wv   = (const float*)d_in[6];
    const float* bv   = (const float*)d_in[7];
    float* out = (float*)d_out;

    float *gv, *gp;
    cudaGetSymbolAddress((void**)&gv, g_v);
    cudaGetSymbolAddress((void**)&gp, g_p);
    __half *xhi, *xlo, *qhi, *khi, *klo, *vthi, *vtlo, *phi;
    __half *wqh, *wql, *wkh, *wkl, *wvh, *wvl;
    cudaGetSymbolAddress((void**)&xhi, g_xhi);   cudaGetSymbolAddress((void**)&xlo, g_xlo);
    cudaGetSymbolAddress((void**)&qhi, g_qhi);
    cudaGetSymbolAddress((void**)&khi, g_khi);   cudaGetSymbolAddress((void**)&klo, g_klo);
    cudaGetSymbolAddress((void**)&vthi, g_vthi); cudaGetSymbolAddress((void**)&vtlo, g_vtlo);
    cudaGetSymbolAddress((void**)&phi, g_phi);
    cudaGetSymbolAddress((void**)&wqh, g_wqh);   cudaGetSymbolAddress((void**)&wql, g_wql);
    cudaGetSymbolAddress((void**)&wkh, g_wkh);   cudaGetSymbolAddress((void**)&wkl, g_wkl);
    cudaGetSymbolAddress((void**)&wvh, g_wvh);   cudaGetSymbolAddress((void**)&wvl, g_wvl);

    const int SMEM4 = 2 * 4 * TILE_B;   // proj (A hi/lo + B hi/lo)
    const int SMEM3 = 2 * 3 * TILE_B;   // scores / PV (A hi + B hi/lo)
    cudaFuncSetAttribute(gemm_f16s<4, true,  true>, cudaFuncAttributeMaxDynamicSharedMemorySize, SMEM4);
    cudaFuncSetAttribute(gemm_f16s<3, true,  true>, cudaFuncAttributeMaxDynamicSharedMemorySize, SMEM4);
    cudaFuncSetAttribute(gemm_f16s<0, true,  true>, cudaFuncAttributeMaxDynamicSharedMemorySize, SMEM4);
    cudaFuncSetAttribute(gemm_f16s<1, false, true>, cudaFuncAttributeMaxDynamicSharedMemorySize, SMEM3);
    cudaFuncSetAttribute(gemm_f16s<2, false, true>, cudaFuncAttributeMaxDynamicSharedMemorySize, SMEM3);

    const long nx = (long)B_ * S_ * E_;
    const long nw = (long)E_ * E_;

    // 1) splits of x and weights
    split_kernel<<<(unsigned)((nx / 4 + 255) / 256), 256>>>(x, xhi, xlo, nx / 4);
    split_kernel<<<(unsigned)((nw / 4 + 255) / 256), 256>>>(wq, wqh, wql, nw / 4);
    split_kernel<<<(unsigned)((nw / 4 + 255) / 256), 256>>>(wk, wkh, wkl, nw / 4);
    split_kernel<<<(unsigned)((nw / 4 + 255) / 256), 256>>>(wv, wvh, wvl, nw / 4);

    // 2) projections (3-term MMA): Q -> hi only; K -> hi+lo; V -> fp32
    const dim3 gproj(E_ / 128, (B_ * S_) / 128, 1);
    gemm_f16s<4, true, true><<<gproj, 256, SMEM4>>>(xhi, xlo, wqh, wql, bq, nullptr,
                                                    nullptr, qhi, nullptr, E_, E_, 0, 0, 0, 1.0f);
    gemm_f16s<3, true, true><<<gproj, 256, SMEM4>>>(xhi, xlo, wkh, wkl, bk, nullptr,
                                                    nullptr, khi, klo, E_, E_, 0, 0, 0, 1.0f);
    gemm_f16s<0, true, true><<<gproj, 256, SMEM4>>>(xhi, xlo, wvh, wvl, bv, nullptr,
                                                    gv, nullptr, nullptr, E_, E_, 0, 0, 0, 1.0f);

    // 3) transpose+split V
    transpose_split_kernel<<<dim3(E_ / 32, S_ / 32, B_), dim3(32, 8)>>>(gv, vthi, vtlo);

    // 4) scores (2-term: QhKh + QhKl), *scale, mask -> -1e30, fp32 out
    const float scale = 0.044194173824159216f;  // 512^-0.5
    const dim3 gsc(S_ / 128, S_ / 128, B_);
    gemm_f16s<1, false, true><<<gsc, 256, SMEM3>>>(qhi, nullptr, khi, klo, nullptr, mask,
                                                   gp, nullptr, nullptr, E_, S_,
                                                   (long)S_ * E_, (long)S_ * E_,
                                                   (long)S_ * S_, scale);

    // 5) softmax -> P hi
    softmax_kernel<<<B_ * S_, 256>>>(gp, phi);

    // 6) out = P . V  (2-term: PhVh + PhVl), fp32 out
    const dim3 gpv(E_ / 128, S_ / 128, B_);
    gemm_f16s<2, false, true><<<gpv, 256, SMEM3>>>(phi, nullptr, vthi, vtlo, nullptr, nullptr,
                                                   out, nullptr, nullptr, S_, E_,
                                                   (long)S_ * S_, (long)E_ * S_,
                                                   (long)S_ * E_, 1.0f);
}

// round 6
// speedup vs baseline: 3.4233x; 1.3408x over previous
#include <cuda_runtime.h>
#include <cuda_fp16.h>
#include <cstdint>

#define B_ 8
#define S_ 2048
#define E_ 512

// ---------------- scratch (__device__ globals; no allocs allowed) ----------
__device__ __align__(16) float g_v[(size_t)B_ * S_ * E_];
__device__ __align__(16) float g_p[(size_t)B_ * S_ * S_];

__device__ __align__(16) __half g_xhi[(size_t)B_ * S_ * E_];
__device__ __align__(16) __half g_qhi[(size_t)B_ * S_ * E_];
__device__ __align__(16) __half g_khi[(size_t)B_ * S_ * E_];
__device__ __align__(16) __half g_klo[(size_t)B_ * S_ * E_];
__device__ __align__(16) __half g_vthi[(size_t)B_ * E_ * S_];  // [B][E][S]
__device__ __align__(16) __half g_phi[(size_t)B_ * S_ * S_];
__device__ __align__(16) __half g_wqh[E_ * E_], g_wql[E_ * E_];
__device__ __align__(16) __half g_wkh[E_ * E_], g_wkl[E_ * E_];
__device__ __align__(16) __half g_wvh[E_ * E_], g_wvl[E_ * E_];

// ---------------- helpers ---------------------------------------------------
__device__ __forceinline__ uint32_t smem_u32(const void* p) {
    uint32_t a;
    asm("{ .reg .u64 t; cvta.to.shared.u64 t, %1; cvt.u32.u64 %0, t; }"
        : "=r"(a) : "l"(p));
    return a;
}
__device__ __forceinline__ void cp16(uint32_t dst, const void* src) {
    asm volatile("cp.async.cg.shared.global [%0], [%1], 16;"
                 :: "r"(dst), "l"(src) : "memory");
}
__device__ __forceinline__ void cp_commit() {
    asm volatile("cp.async.commit_group;" ::: "memory");
}
template <int N>
__device__ __forceinline__ void cp_wait() {
    asm volatile("cp.async.wait_group %0;" :: "n"(N) : "memory");
}
__device__ __forceinline__ void ldm_x4(uint32_t& r0, uint32_t& r1, uint32_t& r2,
                                       uint32_t& r3, uint32_t addr) {
    asm volatile("ldmatrix.sync.aligned.m8n8.x4.shared.b16 {%0,%1,%2,%3}, [%4];"
                 : "=r"(r0), "=r"(r1), "=r"(r2), "=r"(r3) : "r"(addr));
}
__device__ __forceinline__ void mma16816(float* d, const uint32_t* a, const uint32_t* b) {
    asm volatile("mma.sync.aligned.m16n8k16.row.col.f32.f16.f16.f32 "
                 "{%0,%1,%2,%3}, {%4,%5,%6,%7}, {%8,%9}, {%0,%1,%2,%3};"
                 : "+f"(d[0]), "+f"(d[1]), "+f"(d[2]), "+f"(d[3])
                 : "r"(a[0]), "r"(a[1]), "r"(a[2]), "r"(a[3]), "r"(b[0]), "r"(b[1]));
}

// ---------------------------------------------------------------------------
// NT GEMM via fp16 split MMAs:
//   C = scale * (A . B^T) (+ epilogue).  A=[M,K] (hi[,lo]), B=[N,K] (hi[,lo]).
// MMA terms: AhBh (+AhBl if BLO) (+AlBh if ALO).
// Block 128x128, 8 warps (4m x 2n), warp tile 32x64, KC=32, double-buffered.
// EPI: 0 = +bias -> fp32 C
//      1 = *scale, mask>0 -> -1e30 -> fp32 C
//      2 = plain fp32 C
//      3 = +bias -> half outH + half outL
//      4 = +bias -> half outH only
// ---------------------------------------------------------------------------
#define KC 32
#define TSTR 40                        // padded halfs per smem row
#define TILE_B (128 * TSTR * 2)        // 10240 bytes per tile

template <int EPI, bool ALO, bool BLO>
__global__ void __launch_bounds__(256)
gemm_f16s(const __half* __restrict__ Ahi, const __half* __restrict__ Alo,
          const __half* __restrict__ Bhi, const __half* __restrict__ Blo,
          const float* __restrict__ bias, const int* __restrict__ mask,
          float* __restrict__ C, __half* __restrict__ outH, __half* __restrict__ outL,
          int K, int N, long sA, long sB, long sC, float scale)
{
    constexpr uint32_t oAH = 0;
    constexpr uint32_t oAL = TILE_B;                              // valid iff ALO
    constexpr uint32_t oBH = (ALO ? 2u : 1u) * TILE_B;
    constexpr uint32_t oBL = oBH + TILE_B;                        // valid iff BLO
    constexpr uint32_t STAGE_B = (2u + (ALO ? 1u : 0u) + (BLO ? 1u : 0u)) * TILE_B;

    extern __shared__ __align__(16) char sm[];
    const uint32_t sb = smem_u32(sm);

    const int tid  = threadIdx.x;
    const int lane = tid & 31;
    const int wid  = tid >> 5;
    const int warp_m = wid & 3;
    const int warp_n = wid >> 2;

    const int bz = blockIdx.z;
    Ahi += (long)bz * sA;
    if (ALO) Alo += (long)bz * sA;
    Bhi += (long)bz * sB;
    if (BLO) Blo += (long)bz * sB;
    if (EPI == 1) mask += (long)bz * sC;
    if (EPI == 0 || EPI == 1 || EPI == 2) C += (long)bz * sC;
    if (EPI == 3 || EPI == 4) outH += (long)bz * sC;
    if (EPI == 3) outL += (long)bz * sC;
    const int bm = blockIdx.y * 128;
    const int bn = blockIdx.x * 128;

    const int lr = tid >> 2;           // row 0..63 (two passes -> 128)
    const int ls = tid & 3;            // 16B segment
    auto load_chunk = [&](int c) {
        const uint32_t st = sb + (uint32_t)(c & 1) * STAGE_B;
        const int k0 = c * KC;
#pragma unroll
        for (int t = 0; t < 2; ++t) {
            const int r = lr + t * 64;
            const uint32_t so = (uint32_t)(r * (TSTR * 2) + ls * 16);
            const long ga = (long)(bm + r) * K + k0 + ls * 8;
            const long gb = (long)(bn + r) * K + k0 + ls * 8;
            cp16(st + oAH + so, Ahi + ga);
            if (ALO) cp16(st + oAL + so, Alo + ga);
            cp16(st + oBH + so, Bhi + gb);
            if (BLO) cp16(st + oBL + so, Blo + gb);
        }
        cp_commit();
    };

    float acc[2][8][4];
#pragma unroll
    for (int mi = 0; mi < 2; ++mi)
#pragma unroll
        for (int ni = 0; ni < 8; ++ni)
#pragma unroll
            for (int r = 0; r < 4; ++r) acc[mi][ni][r] = 0.0f;

    const int quad = lane >> 3, lm8 = lane & 7;
    const int a_row = warp_m * 32 + lm8 + (quad & 1) * 8;
    const int a_col = (quad >> 1) * 8;
    const int b_row = warp_n * 64 + lm8 + (quad >> 1) * 8;
    const int b_col = (quad & 1) * 8;

    const int nch = K / KC;
    load_chunk(0);
    for (int c = 0; c < nch; ++c) {
        if (c + 1 < nch) { load_chunk(c + 1); cp_wait<1>(); }
        else             { cp_wait<0>(); }
        __syncthreads();

        const uint32_t st = sb + (uint32_t)(c & 1) * STAGE_B;
#pragma unroll
        for (int ks = 0; ks < KC; ks += 16) {
            uint32_t ah[2][4], al[2][4], bh[8][2], bl[8][2];
#pragma unroll
            for (int mi = 0; mi < 2; ++mi) {
                const uint32_t ao =
                    (uint32_t)(((a_row + mi * 16) * TSTR + a_col + ks) * 2);
                ldm_x4(ah[mi][0], ah[mi][1], ah[mi][2], ah[mi][3], st + oAH + ao);
                if (ALO)
                    ldm_x4(al[mi][0], al[mi][1], al[mi][2], al[mi][3], st + oAL + ao);
            }
#pragma unroll
            for (int np = 0; np < 4; ++np) {
                const uint32_t bo =
                    (uint32_t)(((b_row + np * 16) * TSTR + b_col + ks) * 2);
                ldm_x4(bh[2 * np][0], bh[2 * np][1], bh[2 * np + 1][0], bh[2 * np + 1][1],
                       st + oBH + bo);
                if (BLO)
                    ldm_x4(bl[2 * np][0], bl[2 * np][1], bl[2 * np + 1][0], bl[2 * np + 1][1],
                           st + oBL + bo);
            }
#pragma unroll
            for (int mi = 0; mi < 2; ++mi)
#pragma unroll
                for (int ni = 0; ni < 8; ++ni) {
                    mma16816(acc[mi][ni], ah[mi], bh[ni]);
                    if (BLO) mma16816(acc[mi][ni], ah[mi], bl[ni]);
                    if (ALO) mma16816(acc[mi][ni], al[mi], bh[ni]);
                }
        }
        __syncthreads();
    }

    // ---- epilogue ----
#pragma unroll
    for (int mi = 0; mi < 2; ++mi)
#pragma unroll
        for (int ni = 0; ni < 8; ++ni) {
            const int row0 = bm + warp_m * 32 + mi * 16 + (lane >> 2);
            const int col0 = bn + warp_n * 64 + ni * 8 + (lane & 3) * 2;
            float c0 = acc[mi][ni][0], c1 = acc[mi][ni][1];
            float c2 = acc[mi][ni][2], c3 = acc[mi][ni][3];
            if (EPI == 0 || EPI == 3 || EPI == 4) {
                const float2 bb = *reinterpret_cast<const float2*>(&bias[col0]);
                c0 += bb.x; c1 += bb.y; c2 += bb.x; c3 += bb.y;
            }
            if (EPI == 1) {
                c0 *= scale; c1 *= scale; c2 *= scale; c3 *= scale;
                const int2 ma = *reinterpret_cast<const int2*>(&mask[(long)row0 * N + col0]);
                const int2 mb = *reinterpret_cast<const int2*>(&mask[(long)(row0 + 8) * N + col0]);
                if (ma.x > 0) c0 = -1e30f;
                if (ma.y > 0) c1 = -1e30f;
                if (mb.x > 0) c2 = -1e30f;
                if (mb.y > 0) c3 = -1e30f;
            }
            if (EPI == 3 || EPI == 4) {
                const __half h0 = __float2half_rn(c0), h1 = __float2half_rn(c1);
                const __half h2 = __float2half_rn(c2), h3 = __float2half_rn(c3);
                *reinterpret_cast<__half2*>(&outH[(long)row0 * N + col0]) =
                    __halves2half2(h0, h1);
                *reinterpret_cast<__half2*>(&outH[(long)(row0 + 8) * N + col0]) =
                    __halves2half2(h2, h3);
                if (EPI == 3) {
                    const __half l0 = __float2half_rn(c0 - __half2float(h0));
                    const __half l1 = __float2half_rn(c1 - __half2float(h1));
                    const __half l2 = __float2half_rn(c2 - __half2float(h2));
                    const __half l3 = __float2half_rn(c3 - __half2float(h3));
                    *reinterpret_cast<__half2*>(&outL[(long)row0 * N + col0]) =
                        __halves2half2(l0, l1);
                    *reinterpret_cast<__half2*>(&outL[(long)(row0 + 8) * N + col0]) =
                        __halves2half2(l2, l3);
                }
            } else {
                *reinterpret_cast<float2*>(&C[(long)row0 * N + col0]) = make_float2(c0, c1);
                *reinterpret_cast<float2*>(&C[(long)(row0 + 8) * N + col0]) = make_float2(c2, c3);
            }
        }
}

// ---------------------------------------------------------------------------
// fp32 -> hi/lo fp16 splits
// ---------------------------------------------------------------------------
__global__ void __launch_bounds__(256)
split_kernel(const float* __restrict__ src, __half* __restrict__ hi,
             __half* __restrict__ lo, long n4)
{
    const long i = (long)blockIdx.x * blockDim.x + threadIdx.x;
    if (i >= n4) return;
    const float4 v = reinterpret_cast<const float4*>(src)[i];
    const __half h0 = __float2half_rn(v.x), h1 = __float2half_rn(v.y);
    const __half h2 = __float2half_rn(v.z), h3 = __float2half_rn(v.w);
    const __half l0 = __float2half_rn(v.x - __half2float(h0));
    const __half l1 = __float2half_rn(v.y - __half2float(h1));
    const __half l2 = __float2half_rn(v.z - __half2float(h2));
    const __half l3 = __float2half_rn(v.w - __half2float(h3));
    __half2* hi2 = reinterpret_cast<__half2*>(hi);
    __half2* lo2 = reinterpret_cast<__half2*>(lo);
    hi2[2 * i]     = __halves2half2(h0, h1);
    hi2[2 * i + 1] = __halves2half2(h2, h3);
    lo2[2 * i]     = __halves2half2(l0, l1);
    lo2[2 * i + 1] = __halves2half2(l2, l3);
}

__global__ void __launch_bounds__(256)
split_hi_kernel(const float* __restrict__ src, __half* __restrict__ hi, long n4)
{
    const long i = (long)blockIdx.x * blockDim.x + threadIdx.x;
    if (i >= n4) return;
    const float4 v = reinterpret_cast<const float4*>(src)[i];
    __half2* hi2 = reinterpret_cast<__half2*>(hi);
    hi2[2 * i]     = __halves2half2(__float2half_rn(v.x), __float2half_rn(v.y));
    hi2[2 * i + 1] = __halves2half2(__float2half_rn(v.z), __float2half_rn(v.w));
}

// ---------------------------------------------------------------------------
// V [B][S][E] fp32 -> Vt hi [B][E][S] fp16 (tiled transpose, hi only)
// ---------------------------------------------------------------------------
__global__ void __launch_bounds__(256)
transpose_hi_kernel(const float* __restrict__ v, __half* __restrict__ th)
{
    __shared__ float t[32][33];
    const int b = blockIdx.z;
    const int e0 = blockIdx.x * 32;
    const int s0 = blockIdx.y * 32;
    const int tx = threadIdx.x, ty = threadIdx.y;  // 32 x 8
#pragma unroll
    for (int j = 0; j < 4; ++j) {
        const int s = s0 + ty + j * 8;
        t[ty + j * 8][tx] = v[((long)b * S_ + s) * E_ + e0 + tx];
    }
    __syncthreads();
#pragma unroll
    for (int j = 0; j < 4; ++j) {
        const int e = e0 + ty + j * 8;
        th[((long)b * E_ + e) * S_ + s0 + tx] = __float2half_rn(t[tx][ty + j * 8]);
    }
}

// ---------------------------------------------------------------------------
// Row softmax over fp32 scores; emits P hi (fp16) only.
// ---------------------------------------------------------------------------
__global__ void __launch_bounds__(256)
softmax_kernel(const float* __restrict__ P, __half* __restrict__ phi)
{
    const float* p = P + (long)blockIdx.x * S_;
    __half* oh = phi + (long)blockIdx.x * S_;
    const int tid = threadIdx.x;
    __shared__ float red[256];

    float lmax = -1e30f;
    for (int i = tid; i < S_; i += 256) lmax = fmaxf(lmax, p[i]);
    red[tid] = lmax;
    __syncthreads();
#pragma unroll
    for (int s = 128; s > 0; s >>= 1) {
        if (tid < s) red[tid] = fmaxf(red[tid], red[tid + s]);
        __syncthreads();
    }
    const float m = red[0];
    __syncthreads();

    float lsum = 0.0f;
    float e_cache[8];
#pragma unroll
    for (int j = 0; j < 8; ++j) {
        const float e = __expf(p[tid + j * 256] - m);
        e_cache[j] = e;
        lsum += e;
    }
    red[tid] = lsum;
    __syncthreads();
#pragma unroll
    for (int s = 128; s > 0; s >>= 1) {
        if (tid < s) red[tid] += red[tid + s];
        __syncthreads();
    }
    const float inv = 1.0f / red[0];
#pragma unroll
    for (int j = 0; j < 8; ++j)
        oh[tid + j * 256] = __float2half_rn(e_cache[j] * inv);
}

// ---------------------------------------------------------------------------
extern "C" void kernel_launch(void* const* d_in, const int* in_sizes, int n_in,
                              void* d_out, int out_size)
{
    const float* x    = (const float*)d_in[0];
    const int*   mask = (const int*)  d_in[1];
    const float* wq   = (const float*)d_in[2];
    const float* bq   = (const float*)d_in[3];
    const float* wk   = (const float*)d_in[4];
    const float* bk   = (const float*)d_in[5];
    const float* wv   = (const float*)d_in[6];
    const float* bv   = (const float*)d_in[7];
    float* out = (float*)d_out;

    float *gv, *gp;
    cudaGetSymbolAddress((void**)&gv, g_v);
    cudaGetSymbolAddress((void**)&gp, g_p);
    __half *xhi, *qhi, *khi, *klo, *vthi, *phi;
    __half *wqh, *wql, *wkh, *wkl, *wvh, *wvl;
    cudaGetSymbolAddress((void**)&xhi, g_xhi);
    cudaGetSymbolAddress((void**)&qhi, g_qhi);
    cudaGetSymbolAddress((void**)&khi, g_khi);   cudaGetSymbolAddress((void**)&klo, g_klo);
    cudaGetSymbolAddress((void**)&vthi, g_vthi);
    cudaGetSymbolAddress((void**)&phi, g_phi);
    cudaGetSymbolAddress((void**)&wqh, g_wqh);   cudaGetSymbolAddress((void**)&wql, g_wql);
    cudaGetSymbolAddress((void**)&wkh, g_wkh);   cudaGetSymbolAddress((void**)&wkl, g_wkl);
    cudaGetSymbolAddress((void**)&wvh, g_wvh);   cudaGetSymbolAddress((void**)&wvl, g_wvl);

    const int SMEM3 = 2 * 3 * TILE_B;   // A hi + B hi/lo
    const int SMEM2 = 2 * 2 * TILE_B;   // A hi + B hi
    cudaFuncSetAttribute(gemm_f16s<4, false, true>,  cudaFuncAttributeMaxDynamicSharedMemorySize, SMEM3);
    cudaFuncSetAttribute(gemm_f16s<3, false, true>,  cudaFuncAttributeMaxDynamicSharedMemorySize, SMEM3);
    cudaFuncSetAttribute(gemm_f16s<0, false, true>,  cudaFuncAttributeMaxDynamicSharedMemorySize, SMEM3);
    cudaFuncSetAttribute(gemm_f16s<1, false, true>,  cudaFuncAttributeMaxDynamicSharedMemorySize, SMEM3);
    cudaFuncSetAttribute(gemm_f16s<2, false, false>, cudaFuncAttributeMaxDynamicSharedMemorySize, SMEM2);

    const long nx = (long)B_ * S_ * E_;
    const long nw = (long)E_ * E_;

    // 1) splits: x -> hi only; weights -> hi+lo
    split_hi_kernel<<<(unsigned)((nx / 4 + 255) / 256), 256>>>(x, xhi, nx / 4);
    split_kernel<<<(unsigned)((nw / 4 + 255) / 256), 256>>>(wq, wqh, wql, nw / 4);
    split_kernel<<<(unsigned)((nw / 4 + 255) / 256), 256>>>(wk, wkh, wkl, nw / 4);
    split_kernel<<<(unsigned)((nw / 4 + 255) / 256), 256>>>(wv, wvh, wvl, nw / 4);

    // 2) projections (2-term: xh.Wh + xh.Wl): Q -> hi; K -> hi+lo; V -> fp32
    const dim3 gproj(E_ / 128, (B_ * S_) / 128, 1);
    gemm_f16s<4, false, true><<<gproj, 256, SMEM3>>>(xhi, nullptr, wqh, wql, bq, nullptr,
                                                     nullptr, qhi, nullptr, E_, E_, 0, 0, 0, 1.0f);
    gemm_f16s<3, false, true><<<gproj, 256, SMEM3>>>(xhi, nullptr, wkh, wkl, bk, nullptr,
                                                     nullptr, khi, klo, E_, E_, 0, 0, 0, 1.0f);
    gemm_f16s<0, false, true><<<gproj, 256, SMEM3>>>(xhi, nullptr, wvh, wvl, bv, nullptr,
                                                     gv, nullptr, nullptr, E_, E_, 0, 0, 0, 1.0f);

    // 3) transpose V -> Vt hi
    transpose_hi_kernel<<<dim3(E_ / 32, S_ / 32, B_), dim3(32, 8)>>>(gv, vthi);

    // 4) scores (2-term: QhKh + QhKl), *scale, mask -> -1e30, fp32 out
    const float scale = 0.044194173824159216f;  // 512^-0.5
    const dim3 gsc(S_ / 128, S_ / 128, B_);
    gemm_f16s<1, false, true><<<gsc, 256, SMEM3>>>(qhi, nullptr, khi, klo, nullptr, mask,
                                                   gp, nullptr, nullptr, E_, S_,
                                                   (long)S_ * E_, (long)S_ * E_,
                                                   (long)S_ * S_, scale);

    // 5) softmax -> P hi
    softmax_kernel<<<B_ * S_, 256>>>(gp, phi);

    // 6) out = P . V  (1-term: PhVh), fp32 out
    const dim3 gpv(E_ / 128, S_ / 128, B_);
    gemm_f16s<2, false, false><<<gpv, 256, SMEM2>>>(phi, nullptr, vthi, nullptr, nullptr, nullptr,
                                                    out, nullptr, nullptr, S_, E_,
                                                    (long)S_ * S_, (long)E_ * S_,
                                                    (long)S_ * E_, 1.0f);
}

// round 7
// speedup vs baseline: 4.3716x; 1.2770x over previous
#include <cuda_runtime.h>
#include <cuda_fp16.h>
#include <cstdint>

#define B_ 8
#define S_ 2048
#define E_ 512

// ---------------- scratch (__device__ globals; no allocs allowed) ----------
__device__ __align__(16) float g_v[(size_t)B_ * S_ * E_];
__device__ __align__(16) float g_p[(size_t)B_ * S_ * S_];

__device__ __align__(16) __half g_xhi[(size_t)B_ * S_ * E_];
__device__ __align__(16) __half g_qhi[(size_t)B_ * S_ * E_];
__device__ __align__(16) __half g_khi[(size_t)B_ * S_ * E_];
__device__ __align__(16) __half g_vthi[(size_t)B_ * E_ * S_];  // [B][E][S]
__device__ __align__(16) __half g_phi[(size_t)B_ * S_ * S_];
__device__ __align__(16) __half g_wqh[E_ * E_];
__device__ __align__(16) __half g_wkh[E_ * E_];
__device__ __align__(16) __half g_wvh[E_ * E_], g_wvl[E_ * E_];

// ---------------- helpers ---------------------------------------------------
__device__ __forceinline__ uint32_t smem_u32(const void* p) {
    uint32_t a;
    asm("{ .reg .u64 t; cvta.to.shared.u64 t, %1; cvt.u32.u64 %0, t; }"
        : "=r"(a) : "l"(p));
    return a;
}
__device__ __forceinline__ void cp16(uint32_t dst, const void* src) {
    asm volatile("cp.async.cg.shared.global [%0], [%1], 16;"
                 :: "r"(dst), "l"(src) : "memory");
}
__device__ __forceinline__ void cp_commit() {
    asm volatile("cp.async.commit_group;" ::: "memory");
}
template <int N>
__device__ __forceinline__ void cp_wait() {
    asm volatile("cp.async.wait_group %0;" :: "n"(N) : "memory");
}
__device__ __forceinline__ void ldm_x4(uint32_t& r0, uint32_t& r1, uint32_t& r2,
                                       uint32_t& r3, uint32_t addr) {
    asm volatile("ldmatrix.sync.aligned.m8n8.x4.shared.b16 {%0,%1,%2,%3}, [%4];"
                 : "=r"(r0), "=r"(r1), "=r"(r2), "=r"(r3) : "r"(addr));
}
__device__ __forceinline__ void mma16816(float* d, const uint32_t* a, const uint32_t* b) {
    asm volatile("mma.sync.aligned.m16n8k16.row.col.f32.f16.f16.f32 "
                 "{%0,%1,%2,%3}, {%4,%5,%6,%7}, {%8,%9}, {%0,%1,%2,%3};"
                 : "+f"(d[0]), "+f"(d[1]), "+f"(d[2]), "+f"(d[3])
                 : "r"(a[0]), "r"(a[1]), "r"(a[2]), "r"(a[3]), "r"(b[0]), "r"(b[1]));
}

// ---------------------------------------------------------------------------
// NT GEMM via fp16 MMAs: C = scale * (A . B^T) (+ epilogue).
// A=[M,K] hi, B=[N,K] hi (+lo if BLO; adds Ah.Bl term).
// Block 128x128, 8 warps (4m x 2n), warp tile 32x64, KC=32, double-buffered.
// EPI: 0 = +bias -> fp32 C
//      1 = *scale, mask>0 -> -1e30 -> fp32 C
//      2 = plain fp32 C
//      4 = +bias -> half outH
// ---------------------------------------------------------------------------
#define KC 32
#define TSTR 40                        // padded halfs per smem row
#define TILE_B (128 * TSTR * 2)        // 10240 bytes per tile

template <int EPI, bool BLO>
__global__ void __launch_bounds__(256)
gemm_f16s(const __half* __restrict__ Ahi, const __half* __restrict__ Bhi,
          const __half* __restrict__ Blo,
          const float* __restrict__ bias, const int* __restrict__ mask,
          float* __restrict__ C, __half* __restrict__ outH,
          int K, int N, long sA, long sB, long sC, float scale)
{
    constexpr uint32_t oAH = 0;
    constexpr uint32_t oBH = TILE_B;
    constexpr uint32_t oBL = 2u * TILE_B;                         // valid iff BLO
    constexpr uint32_t STAGE_B = (BLO ? 3u : 2u) * TILE_B;

    extern __shared__ __align__(16) char sm[];
    const uint32_t sb = smem_u32(sm);

    const int tid  = threadIdx.x;
    const int lane = tid & 31;
    const int wid  = tid >> 5;
    const int warp_m = wid & 3;
    const int warp_n = wid >> 2;

    const int bz = blockIdx.z;
    Ahi += (long)bz * sA;
    Bhi += (long)bz * sB;
    if (BLO) Blo += (long)bz * sB;
    if (EPI == 1) mask += (long)bz * sC;
    if (EPI == 0 || EPI == 1 || EPI == 2) C += (long)bz * sC;
    if (EPI == 4) outH += (long)bz * sC;
    const int bm = blockIdx.y * 128;
    const int bn = blockIdx.x * 128;

    const int lr = tid >> 2;           // row 0..63 (two passes -> 128)
    const int ls = tid & 3;            // 16B segment
    auto load_chunk = [&](int c) {
        const uint32_t st = sb + (uint32_t)(c & 1) * STAGE_B;
        const int k0 = c * KC;
#pragma unroll
        for (int t = 0; t < 2; ++t) {
            const int r = lr + t * 64;
            const uint32_t so = (uint32_t)(r * (TSTR * 2) + ls * 16);
            const long ga = (long)(bm + r) * K + k0 + ls * 8;
            const long gb = (long)(bn + r) * K + k0 + ls * 8;
            cp16(st + oAH + so, Ahi + ga);
            cp16(st + oBH + so, Bhi + gb);
            if (BLO) cp16(st + oBL + so, Blo + gb);
        }
        cp_commit();
    };

    float acc[2][8][4];
#pragma unroll
    for (int mi = 0; mi < 2; ++mi)
#pragma unroll
        for (int ni = 0; ni < 8; ++ni)
#pragma unroll
            for (int r = 0; r < 4; ++r) acc[mi][ni][r] = 0.0f;

    const int quad = lane >> 3, lm8 = lane & 7;
    const int a_row = warp_m * 32 + lm8 + (quad & 1) * 8;
    const int a_col = (quad >> 1) * 8;
    const int b_row = warp_n * 64 + lm8 + (quad >> 1) * 8;
    const int b_col = (quad & 1) * 8;

    const int nch = K / KC;
    load_chunk(0);
    for (int c = 0; c < nch; ++c) {
        if (c + 1 < nch) { load_chunk(c + 1); cp_wait<1>(); }
        else             { cp_wait<0>(); }
        __syncthreads();

        const uint32_t st = sb + (uint32_t)(c & 1) * STAGE_B;
#pragma unroll
        for (int ks = 0; ks < KC; ks += 16) {
            uint32_t ah[2][4], bh[8][2], bl[8][2];
#pragma unroll
            for (int mi = 0; mi < 2; ++mi) {
                const uint32_t ao =
                    (uint32_t)(((a_row + mi * 16) * TSTR + a_col + ks) * 2);
                ldm_x4(ah[mi][0], ah[mi][1], ah[mi][2], ah[mi][3], st + oAH + ao);
            }
#pragma unroll
            for (int np = 0; np < 4; ++np) {
                const uint32_t bo =
                    (uint32_t)(((b_row + np * 16) * TSTR + b_col + ks) * 2);
                ldm_x4(bh[2 * np][0], bh[2 * np][1], bh[2 * np + 1][0], bh[2 * np + 1][1],
                       st + oBH + bo);
                if (BLO)
                    ldm_x4(bl[2 * np][0], bl[2 * np][1], bl[2 * np + 1][0], bl[2 * np + 1][1],
                           st + oBL + bo);
            }
#pragma unroll
            for (int mi = 0; mi < 2; ++mi)
#pragma unroll
                for (int ni = 0; ni < 8; ++ni) {
                    mma16816(acc[mi][ni], ah[mi], bh[ni]);
                    if (BLO) mma16816(acc[mi][ni], ah[mi], bl[ni]);
                }
        }
        __syncthreads();
    }

    // ---- epilogue ----
#pragma unroll
    for (int mi = 0; mi < 2; ++mi)
#pragma unroll
        for (int ni = 0; ni < 8; ++ni) {
            const int row0 = bm + warp_m * 32 + mi * 16 + (lane >> 2);
            const int col0 = bn + warp_n * 64 + ni * 8 + (lane & 3) * 2;
            float c0 = acc[mi][ni][0], c1 = acc[mi][ni][1];
            float c2 = acc[mi][ni][2], c3 = acc[mi][ni][3];
            if (EPI == 0 || EPI == 4) {
                const float2 bb = *reinterpret_cast<const float2*>(&bias[col0]);
                c0 += bb.x; c1 += bb.y; c2 += bb.x; c3 += bb.y;
            }
            if (EPI == 1) {
                c0 *= scale; c1 *= scale; c2 *= scale; c3 *= scale;
                const int2 ma = *reinterpret_cast<const int2*>(&mask[(long)row0 * N + col0]);
                const int2 mb = *reinterpret_cast<const int2*>(&mask[(long)(row0 + 8) * N + col0]);
                if (ma.x > 0) c0 = -1e30f;
                if (ma.y > 0) c1 = -1e30f;
                if (mb.x > 0) c2 = -1e30f;
                if (mb.y > 0) c3 = -1e30f;
            }
            if (EPI == 4) {
                *reinterpret_cast<__half2*>(&outH[(long)row0 * N + col0]) =
                    __halves2half2(__float2half_rn(c0), __float2half_rn(c1));
                *reinterpret_cast<__half2*>(&outH[(long)(row0 + 8) * N + col0]) =
                    __halves2half2(__float2half_rn(c2), __float2half_rn(c3));
            } else {
                *reinterpret_cast<float2*>(&C[(long)row0 * N + col0]) = make_float2(c0, c1);
                *reinterpret_cast<float2*>(&C[(long)(row0 + 8) * N + col0]) = make_float2(c2, c3);
            }
        }
}

// ---------------------------------------------------------------------------
// fp32 -> fp16 splits
// ---------------------------------------------------------------------------
__global__ void __launch_bounds__(256)
split_kernel(const float* __restrict__ src, __half* __restrict__ hi,
             __half* __restrict__ lo, long n4)
{
    const long i = (long)blockIdx.x * blockDim.x + threadIdx.x;
    if (i >= n4) return;
    const float4 v = reinterpret_cast<const float4*>(src)[i];
    const __half h0 = __float2half_rn(v.x), h1 = __float2half_rn(v.y);
    const __half h2 = __float2half_rn(v.z), h3 = __float2half_rn(v.w);
    const __half l0 = __float2half_rn(v.x - __half2float(h0));
    const __half l1 = __float2half_rn(v.y - __half2float(h1));
    const __half l2 = __float2half_rn(v.z - __half2float(h2));
    const __half l3 = __float2half_rn(v.w - __half2float(h3));
    __half2* hi2 = reinterpret_cast<__half2*>(hi);
    __half2* lo2 = reinterpret_cast<__half2*>(lo);
    hi2[2 * i]     = __halves2half2(h0, h1);
    hi2[2 * i + 1] = __halves2half2(h2, h3);
    lo2[2 * i]     = __halves2half2(l0, l1);
    lo2[2 * i + 1] = __halves2half2(l2, l3);
}

__global__ void __launch_bounds__(256)
split_hi_kernel(const float* __restrict__ src, __half* __restrict__ hi, long n4)
{
    const long i = (long)blockIdx.x * blockDim.x + threadIdx.x;
    if (i >= n4) return;
    const float4 v = reinterpret_cast<const float4*>(src)[i];
    __half2* hi2 = reinterpret_cast<__half2*>(hi);
    hi2[2 * i]     = __halves2half2(__float2half_rn(v.x), __float2half_rn(v.y));
    hi2[2 * i + 1] = __halves2half2(__float2half_rn(v.z), __float2half_rn(v.w));
}

// ---------------------------------------------------------------------------
// V [B][S][E] fp32 -> Vt hi [B][E][S] fp16 (tiled transpose, hi only)
// ---------------------------------------------------------------------------
__global__ void __launch_bounds__(256)
transpose_hi_kernel(const float* __restrict__ v, __half* __restrict__ th)
{
    __shared__ float t[32][33];
    const int b = blockIdx.z;
    const int e0 = blockIdx.x * 32;
    const int s0 = blockIdx.y * 32;
    const int tx = threadIdx.x, ty = threadIdx.y;  // 32 x 8
#pragma unroll
    for (int j = 0; j < 4; ++j) {
        const int s = s0 + ty + j * 8;
        t[ty + j * 8][tx] = v[((long)b * S_ + s) * E_ + e0 + tx];
    }
    __syncthreads();
#pragma unroll
    for (int j = 0; j < 4; ++j) {
        const int e = e0 + ty + j * 8;
        th[((long)b * E_ + e) * S_ + s0 + tx] = __float2half_rn(t[tx][ty + j * 8]);
    }
}

// ---------------------------------------------------------------------------
// Row softmax over fp32 scores; emits P hi (fp16) only.
// ---------------------------------------------------------------------------
__global__ void __launch_bounds__(256)
softmax_kernel(const float* __restrict__ P, __half* __restrict__ phi)
{
    const float* p = P + (long)blockIdx.x * S_;
    __half* oh = phi + (long)blockIdx.x * S_;
    const int tid = threadIdx.x;
    __shared__ float red[256];

    float lmax = -1e30f;
    for (int i = tid; i < S_; i += 256) lmax = fmaxf(lmax, p[i]);
    red[tid] = lmax;
    __syncthreads();
#pragma unroll
    for (int s = 128; s > 0; s >>= 1) {
        if (tid < s) red[tid] = fmaxf(red[tid], red[tid + s]);
        __syncthreads();
    }
    const float m = red[0];
    __syncthreads();

    float lsum = 0.0f;
    float e_cache[8];
#pragma unroll
    for (int j = 0; j < 8; ++j) {
        const float e = __expf(p[tid + j * 256] - m);
        e_cache[j] = e;
        lsum += e;
    }
    red[tid] = lsum;
    __syncthreads();
#pragma unroll
    for (int s = 128; s > 0; s >>= 1) {
        if (tid < s) red[tid] += red[tid + s];
        __syncthreads();
    }
    const float inv = 1.0f / red[0];
#pragma unroll
    for (int j = 0; j < 8; ++j)
        oh[tid + j * 256] = __float2half_rn(e_cache[j] * inv);
}

// ---------------------------------------------------------------------------
extern "C" void kernel_launch(void* const* d_in, const int* in_sizes, int n_in,
                              void* d_out, int out_size)
{
    const float* x    = (const float*)d_in[0];
    const int*   mask = (const int*)  d_in[1];
    const float* wq   = (const float*)d_in[2];
    const float* bq   = (const float*)d_in[3];
    const float* wk   = (const float*)d_in[4];
    const float* bk   = (const float*)d_in[5];
    const float* wv   = (const float*)d_in[6];
    const float* bv   = (const float*)d_in[7];
    float* out = (float*)d_out;

    float *gv, *gp;
    cudaGetSymbolAddress((void**)&gv, g_v);
    cudaGetSymbolAddress((void**)&gp, g_p);
    __half *xhi, *qhi, *khi, *vthi, *phi;
    __half *wqh, *wkh, *wvh, *wvl;
    cudaGetSymbolAddress((void**)&xhi, g_xhi);
    cudaGetSymbolAddress((void**)&qhi, g_qhi);
    cudaGetSymbolAddress((void**)&khi, g_khi);
    cudaGetSymbolAddress((void**)&vthi, g_vthi);
    cudaGetSymbolAddress((void**)&phi, g_phi);
    cudaGetSymbolAddress((void**)&wqh, g_wqh);
    cudaGetSymbolAddress((void**)&wkh, g_wkh);
    cudaGetSymbolAddress((void**)&wvh, g_wvh);   cudaGetSymbolAddress((void**)&wvl, g_wvl);

    const int SMEM3 = 2 * 3 * TILE_B;   // A hi + B hi/lo
    const int SMEM2 = 2 * 2 * TILE_B;   // A hi + B hi
    cudaFuncSetAttribute(gemm_f16s<4, false>, cudaFuncAttributeMaxDynamicSharedMemorySize, SMEM2);
    cudaFuncSetAttribute(gemm_f16s<0, true>,  cudaFuncAttributeMaxDynamicSharedMemorySize, SMEM3);
    cudaFuncSetAttribute(gemm_f16s<1, false>, cudaFuncAttributeMaxDynamicSharedMemorySize, SMEM2);
    cudaFuncSetAttribute(gemm_f16s<2, false>, cudaFuncAttributeMaxDynamicSharedMemorySize, SMEM2);

    const long nx = (long)B_ * S_ * E_;
    const long nw = (long)E_ * E_;

    // 1) splits: x, wq, wk -> hi only; wv -> hi+lo
    split_hi_kernel<<<(unsigned)((nx / 4 + 255) / 256), 256>>>(x, xhi, nx / 4);
    split_hi_kernel<<<(unsigned)((nw / 4 + 255) / 256), 256>>>(wq, wqh, nw / 4);
    split_hi_kernel<<<(unsigned)((nw / 4 + 255) / 256), 256>>>(wk, wkh, nw / 4);
    split_kernel<<<(unsigned)((nw / 4 + 255) / 256), 256>>>(wv, wvh, wvl, nw / 4);

    // 2) projections: Q,K 1-term -> fp16; V 2-term -> fp32
    const dim3 gproj(E_ / 128, (B_ * S_) / 128, 1);
    gemm_f16s<4, false><<<gproj, 256, SMEM2>>>(xhi, wqh, nullptr, bq, nullptr,
                                               nullptr, qhi, E_, E_, 0, 0, 0, 1.0f);
    gemm_f16s<4, false><<<gproj, 256, SMEM2>>>(xhi, wkh, nullptr, bk, nullptr,
                                               nullptr, khi, E_, E_, 0, 0, 0, 1.0f);
    gemm_f16s<0, true><<<gproj, 256, SMEM3>>>(xhi, wvh, wvl, bv, nullptr,
                                              gv, nullptr, E_, E_, 0, 0, 0, 1.0f);

    // 3) transpose V -> Vt hi
    transpose_hi_kernel<<<dim3(E_ / 32, S_ / 32, B_), dim3(32, 8)>>>(gv, vthi);

    // 4) scores (1-term: QhKh), *scale, mask -> -1e30, fp32 out
    const float scale = 0.044194173824159216f;  // 512^-0.5
    const dim3 gsc(S_ / 128, S_ / 128, B_);
    gemm_f16s<1, false><<<gsc, 256, SMEM2>>>(qhi, khi, nullptr, nullptr, mask,
                                             gp, nullptr, E_, S_,
                                             (long)S_ * E_, (long)S_ * E_,
                                             (long)S_ * S_, scale);

    // 5) softmax -> P hi
    softmax_kernel<<<B_ * S_, 256>>>(gp, phi);

    // 6) out = P . V  (1-term: PhVh), fp32 out
    const dim3 gpv(E_ / 128, S_ / 128, B_);
    gemm_f16s<2, false><<<gpv, 256, SMEM2>>>(phi, vthi, nullptr, nullptr, nullptr,
                                             out, nullptr, S_, E_,
                                             (long)S_ * S_, (long)E_ * S_,
                                             (long)S_ * E_, 1.0f);
}

// round 8
// speedup vs baseline: 5.3448x; 1.2226x over previous
#include <cuda_runtime.h>
#include <cuda_fp16.h>
#include <cstdint>

#define B_ 8
#define S_ 2048
#define E_ 512

// ---------------- scratch (__device__ globals; no allocs allowed) ----------
__device__ __align__(16) float g_v[(size_t)B_ * S_ * E_];

__device__ __align__(16) __half g_xhi[(size_t)B_ * S_ * E_];
__device__ __align__(16) __half g_qhi[(size_t)B_ * S_ * E_];
__device__ __align__(16) __half g_khi[(size_t)B_ * S_ * E_];
__device__ __align__(16) __half g_vthi[(size_t)B_ * E_ * S_];  // [B][E][S]
__device__ __align__(16) __half g_phi[(size_t)B_ * S_ * S_];   // unnormalized exp
__device__ __align__(16) __half g_wqh[E_ * E_];
__device__ __align__(16) __half g_wkh[E_ * E_];
__device__ __align__(16) __half g_wvh[E_ * E_];
__device__ __align__(16) float g_psum[16 * B_ * S_];           // [tileN][B*S]
__device__ __align__(16) float g_Z[B_ * S_];                   // row sums

// ---------------- helpers ---------------------------------------------------
__device__ __forceinline__ uint32_t smem_u32(const void* p) {
    uint32_t a;
    asm("{ .reg .u64 t; cvta.to.shared.u64 t, %1; cvt.u32.u64 %0, t; }"
        : "=r"(a) : "l"(p));
    return a;
}
__device__ __forceinline__ void cp16(uint32_t dst, const void* src) {
    asm volatile("cp.async.cg.shared.global [%0], [%1], 16;"
                 :: "r"(dst), "l"(src) : "memory");
}
__device__ __forceinline__ void cp_commit() {
    asm volatile("cp.async.commit_group;" ::: "memory");
}
template <int N>
__device__ __forceinline__ void cp_wait() {
    asm volatile("cp.async.wait_group %0;" :: "n"(N) : "memory");
}
__device__ __forceinline__ void ldm_x4(uint32_t& r0, uint32_t& r1, uint32_t& r2,
                                       uint32_t& r3, uint32_t addr) {
    asm volatile("ldmatrix.sync.aligned.m8n8.x4.shared.b16 {%0,%1,%2,%3}, [%4];"
                 : "=r"(r0), "=r"(r1), "=r"(r2), "=r"(r3) : "r"(addr));
}
__device__ __forceinline__ void mma16816(float* d, const uint32_t* a, const uint32_t* b) {
    asm volatile("mma.sync.aligned.m16n8k16.row.col.f32.f16.f16.f32 "
                 "{%0,%1,%2,%3}, {%4,%5,%6,%7}, {%8,%9}, {%0,%1,%2,%3};"
                 : "+f"(d[0]), "+f"(d[1]), "+f"(d[2]), "+f"(d[3])
                 : "r"(a[0]), "r"(a[1]), "r"(a[2]), "r"(a[3]), "r"(b[0]), "r"(b[1]));
}

// ---------------------------------------------------------------------------
// NT GEMM, pure fp16 MMA: C-tile = A[M,K] . B[N,K]^T (+ epilogue).
// Block 128x128, 8 warps (4m x 2n), warp tile 32x64, KC=32, double-buffered.
// EPI: 0 = +bias -> fp32 C
//      4 = +bias -> fp16 outH
//      5 = p = (mask>0 ? 0 : exp(scale*s)) -> fp16 outH; row partial sums -> psum
//      6 = acc / Z[row] -> fp32 C
// ---------------------------------------------------------------------------
#define KC 32
#define TSTR 40                        // padded halfs per smem row
#define TILE_B (128 * TSTR * 2)        // 10240 bytes per tile
#define STAGE_B (2 * TILE_B)
#define SMEM_SZ (2 * STAGE_B)          // 40960

template <int EPI>
__global__ void __launch_bounds__(256)
gemm_f16s(const __half* __restrict__ A, const __half* __restrict__ Bm,
          const float* __restrict__ bias, const int* __restrict__ mask,
          float* __restrict__ C, __half* __restrict__ outH,
          float* __restrict__ psum, const float* __restrict__ zrow,
          int K, int N, long sA, long sB, long sC, float scale)
{
    extern __shared__ __align__(16) char sm[];
    const uint32_t sb = smem_u32(sm);

    const int tid  = threadIdx.x;
    const int lane = tid & 31;
    const int wid  = tid >> 5;
    const int warp_m = wid & 3;
    const int warp_n = wid >> 2;

    const int bz = blockIdx.z;
    A  += (long)bz * sA;
    Bm += (long)bz * sB;
    if (EPI == 5) mask += (long)bz * sC;
    if (EPI == 0 || EPI == 6) C += (long)bz * sC;
    if (EPI == 4 || EPI == 5) outH += (long)bz * sC;
    const int bm = blockIdx.y * 128;
    const int bn = blockIdx.x * 128;

    const int lr = tid >> 2;           // row 0..63 (two passes -> 128)
    const int ls = tid & 3;            // 16B segment
    auto load_chunk = [&](int c) {
        const uint32_t st = sb + (uint32_t)(c & 1) * STAGE_B;
        const int k0 = c * KC;
#pragma unroll
        for (int t = 0; t < 2; ++t) {
            const int r = lr + t * 64;
            const uint32_t so = (uint32_t)(r * (TSTR * 2) + ls * 16);
            cp16(st + so,          A  + (long)(bm + r) * K + k0 + ls * 8);
            cp16(st + TILE_B + so, Bm + (long)(bn + r) * K + k0 + ls * 8);
        }
        cp_commit();
    };

    float acc[2][8][4];
#pragma unroll
    for (int mi = 0; mi < 2; ++mi)
#pragma unroll
        for (int ni = 0; ni < 8; ++ni)
#pragma unroll
            for (int r = 0; r < 4; ++r) acc[mi][ni][r] = 0.0f;

    const int quad = lane >> 3, lm8 = lane & 7;
    const int a_row = warp_m * 32 + lm8 + (quad & 1) * 8;
    const int a_col = (quad >> 1) * 8;
    const int b_row = warp_n * 64 + lm8 + (quad >> 1) * 8;
    const int b_col = (quad & 1) * 8;

    const int nch = K / KC;
    load_chunk(0);
    for (int c = 0; c < nch; ++c) {
        if (c + 1 < nch) { load_chunk(c + 1); cp_wait<1>(); }
        else             { cp_wait<0>(); }
        __syncthreads();

        const uint32_t st = sb + (uint32_t)(c & 1) * STAGE_B;
#pragma unroll
        for (int ks = 0; ks < KC; ks += 16) {
            uint32_t ah[2][4], bh[8][2];
#pragma unroll
            for (int mi = 0; mi < 2; ++mi) {
                const uint32_t ao =
                    (uint32_t)(((a_row + mi * 16) * TSTR + a_col + ks) * 2);
                ldm_x4(ah[mi][0], ah[mi][1], ah[mi][2], ah[mi][3], st + ao);
            }
#pragma unroll
            for (int np = 0; np < 4; ++np) {
                const uint32_t bo =
                    (uint32_t)(((b_row + np * 16) * TSTR + b_col + ks) * 2);
                ldm_x4(bh[2 * np][0], bh[2 * np][1], bh[2 * np + 1][0], bh[2 * np + 1][1],
                       st + TILE_B + bo);
            }
#pragma unroll
            for (int mi = 0; mi < 2; ++mi)
#pragma unroll
                for (int ni = 0; ni < 8; ++ni)
                    mma16816(acc[mi][ni], ah[mi], bh[ni]);
        }
        __syncthreads();
    }

    // ---- epilogue ----
    float invz[2][2];
    if (EPI == 6) {
#pragma unroll
        for (int mi = 0; mi < 2; ++mi)
#pragma unroll
            for (int j = 0; j < 2; ++j) {
                const int row = bm + warp_m * 32 + mi * 16 + (lane >> 2) + j * 8;
                invz[mi][j] = 1.0f / __ldg(&zrow[(long)bz * S_ + row]);
            }
    }
    float rsum[2][2] = {{0.0f, 0.0f}, {0.0f, 0.0f}};

#pragma unroll
    for (int mi = 0; mi < 2; ++mi)
#pragma unroll
        for (int ni = 0; ni < 8; ++ni) {
            const int row0 = bm + warp_m * 32 + mi * 16 + (lane >> 2);
            const int col0 = bn + warp_n * 64 + ni * 8 + (lane & 3) * 2;
            float c0 = acc[mi][ni][0], c1 = acc[mi][ni][1];
            float c2 = acc[mi][ni][2], c3 = acc[mi][ni][3];
            if (EPI == 0 || EPI == 4) {
                const float2 bb = *reinterpret_cast<const float2*>(&bias[col0]);
                c0 += bb.x; c1 += bb.y; c2 += bb.x; c3 += bb.y;
            }
            if (EPI == 5) {
                const int2 ma = *reinterpret_cast<const int2*>(&mask[(long)row0 * N + col0]);
                const int2 mb = *reinterpret_cast<const int2*>(&mask[(long)(row0 + 8) * N + col0]);
                c0 = (ma.x > 0) ? 0.0f : __expf(scale * c0);
                c1 = (ma.y > 0) ? 0.0f : __expf(scale * c1);
                c2 = (mb.x > 0) ? 0.0f : __expf(scale * c2);
                c3 = (mb.y > 0) ? 0.0f : __expf(scale * c3);
                rsum[mi][0] += c0 + c1;
                rsum[mi][1] += c2 + c3;
            }
            if (EPI == 6) {
                c0 *= invz[mi][0]; c1 *= invz[mi][0];
                c2 *= invz[mi][1]; c3 *= invz[mi][1];
            }
            if (EPI == 4 || EPI == 5) {
                *reinterpret_cast<__half2*>(&outH[(long)row0 * N + col0]) =
                    __halves2half2(__float2half_rn(c0), __float2half_rn(c1));
                *reinterpret_cast<__half2*>(&outH[(long)(row0 + 8) * N + col0]) =
                    __halves2half2(__float2half_rn(c2), __float2half_rn(c3));
            } else {
                *reinterpret_cast<float2*>(&C[(long)row0 * N + col0]) = make_float2(c0, c1);
                *reinterpret_cast<float2*>(&C[(long)(row0 + 8) * N + col0]) = make_float2(c2, c3);
            }
        }

    if (EPI == 5) {
        // reduce row sums: shuffle over the 4 lanes sharing a row, then smem
        // across the two warp_n column-halves; write [tileN][B*S] partials.
#pragma unroll
        for (int mi = 0; mi < 2; ++mi)
#pragma unroll
            for (int j = 0; j < 2; ++j) {
                rsum[mi][j] += __shfl_xor_sync(0xFFFFFFFFu, rsum[mi][j], 1);
                rsum[mi][j] += __shfl_xor_sync(0xFFFFFFFFu, rsum[mi][j], 2);
            }
        float* rowbuf = reinterpret_cast<float*>(sm);
        if (tid < 128) rowbuf[tid] = 0.0f;
        __syncthreads();
        if ((lane & 3) == 0) {
#pragma unroll
            for (int mi = 0; mi < 2; ++mi)
#pragma unroll
                for (int j = 0; j < 2; ++j)
                    atomicAdd(&rowbuf[warp_m * 32 + mi * 16 + (lane >> 2) + j * 8],
                              rsum[mi][j]);
        }
        __syncthreads();
        if (tid < 128)
            psum[(long)blockIdx.x * (B_ * S_) + (long)bz * S_ + bm + tid] = rowbuf[tid];
    }
}

// ---------------------------------------------------------------------------
// Z[row] = sum over 16 tile partials
// ---------------------------------------------------------------------------
__global__ void __launch_bounds__(256)
zreduce_kernel(const float* __restrict__ psum, float* __restrict__ z)
{
    const int i = blockIdx.x * 256 + threadIdx.x;
    float s = 0.0f;
#pragma unroll
    for (int k = 0; k < 16; ++k) s += psum[(long)k * (B_ * S_) + i];
    z[i] = s;
}

// ---------------------------------------------------------------------------
// fp32 -> fp16 (hi) cast
// ---------------------------------------------------------------------------
__global__ void __launch_bounds__(256)
split_hi_kernel(const float* __restrict__ src, __half* __restrict__ hi, long n4)
{
    const long i = (long)blockIdx.x * blockDim.x + threadIdx.x;
    if (i >= n4) return;
    const float4 v = reinterpret_cast<const float4*>(src)[i];
    __half2* hi2 = reinterpret_cast<__half2*>(hi);
    hi2[2 * i]     = __halves2half2(__float2half_rn(v.x), __float2half_rn(v.y));
    hi2[2 * i + 1] = __halves2half2(__float2half_rn(v.z), __float2half_rn(v.w));
}

// ---------------------------------------------------------------------------
// V [B][S][E] fp32 -> Vt [B][E][S] fp16 (tiled transpose)
// ---------------------------------------------------------------------------
__global__ void __launch_bounds__(256)
transpose_hi_kernel(const float* __restrict__ v, __half* __restrict__ th)
{
    __shared__ float t[32][33];
    const int b = blockIdx.z;
    const int e0 = blockIdx.x * 32;
    const int s0 = blockIdx.y * 32;
    const int tx = threadIdx.x, ty = threadIdx.y;  // 32 x 8
#pragma unroll
    for (int j = 0; j < 4; ++j) {
        const int s = s0 + ty + j * 8;
        t[ty + j * 8][tx] = v[((long)b * S_ + s) * E_ + e0 + tx];
    }
    __syncthreads();
#pragma unroll
    for (int j = 0; j < 4; ++j) {
        const int e = e0 + ty + j * 8;
        th[((long)b * E_ + e) * S_ + s0 + tx] = __float2half_rn(t[tx][ty + j * 8]);
    }
}

// ---------------------------------------------------------------------------
extern "C" void kernel_launch(void* const* d_in, const int* in_sizes, int n_in,
                              void* d_out, int out_size)
{
    const float* x    = (const float*)d_in[0];
    const int*   mask = (const int*)  d_in[1];
    const float* wq   = (const float*)d_in[2];
    const float* bq   = (const float*)d_in[3];
    const float* wk   = (const float*)d_in[4];
    const float* bk   = (const float*)d_in[5];
    const float* wv   = (const float*)d_in[6];
    const float* bv   = (const float*)d_in[7];
    float* out = (float*)d_out;

    float *gv, *psum, *gz;
    cudaGetSymbolAddress((void**)&gv, g_v);
    cudaGetSymbolAddress((void**)&psum, g_psum);
    cudaGetSymbolAddress((void**)&gz, g_Z);
    __half *xhi, *qhi, *khi, *vthi, *phi, *wqh, *wkh, *wvh;
    cudaGetSymbolAddress((void**)&xhi, g_xhi);
    cudaGetSymbolAddress((void**)&qhi, g_qhi);
    cudaGetSymbolAddress((void**)&khi, g_khi);
    cudaGetSymbolAddress((void**)&vthi, g_vthi);
    cudaGetSymbolAddress((void**)&phi, g_phi);
    cudaGetSymbolAddress((void**)&wqh, g_wqh);
    cudaGetSymbolAddress((void**)&wkh, g_wkh);
    cudaGetSymbolAddress((void**)&wvh, g_wvh);

    const long nx = (long)B_ * S_ * E_;
    const long nw = (long)E_ * E_;

    // 1) fp16 casts
    split_hi_kernel<<<(unsigned)((nx / 4 + 255) / 256), 256>>>(x, xhi, nx / 4);
    split_hi_kernel<<<(unsigned)((nw / 4 + 255) / 256), 256>>>(wq, wqh, nw / 4);
    split_hi_kernel<<<(unsigned)((nw / 4 + 255) / 256), 256>>>(wk, wkh, nw / 4);
    split_hi_kernel<<<(unsigned)((nw / 4 + 255) / 256), 256>>>(wv, wvh, nw / 4);

    // 2) projections (1-term): Q,K -> fp16; V -> fp32
    const dim3 gproj(E_ / 128, (B_ * S_) / 128, 1);
    gemm_f16s<4><<<gproj, 256, SMEM_SZ>>>(xhi, wqh, bq, nullptr, nullptr, qhi,
                                          nullptr, nullptr, E_, E_, 0, 0, 0, 1.0f);
    gemm_f16s<4><<<gproj, 256, SMEM_SZ>>>(xhi, wkh, bk, nullptr, nullptr, khi,
                                          nullptr, nullptr, E_, E_, 0, 0, 0, 1.0f);
    gemm_f16s<0><<<gproj, 256, SMEM_SZ>>>(xhi, wvh, bv, nullptr, gv, nullptr,
                                          nullptr, nullptr, E_, E_, 0, 0, 0, 1.0f);

    // 3) transpose V -> Vt fp16
    transpose_hi_kernel<<<dim3(E_ / 32, S_ / 32, B_), dim3(32, 8)>>>(gv, vthi);

    // 4) scores + mask + max-free exp -> unnormalized P (fp16) + row partials
    const float scale = 0.044194173824159216f;  // 512^-0.5
    const dim3 gsc(S_ / 128, S_ / 128, B_);
    gemm_f16s<5><<<gsc, 256, SMEM_SZ>>>(qhi, khi, nullptr, mask, nullptr, phi,
                                        psum, nullptr, E_, S_,
                                        (long)S_ * E_, (long)S_ * E_,
                                        (long)S_ * S_, scale);

    // 5) Z[row] = sum of partials
    zreduce_kernel<<<(B_ * S_) / 256, 256>>>(psum, gz);

    // 6) out = (P~ . Vt^T) / Z
    const dim3 gpv(E_ / 128, S_ / 128, B_);
    gemm_f16s<6><<<gpv, 256, SMEM_SZ>>>(phi, vthi, nullptr, nullptr, out, nullptr,
                                        nullptr, gz, S_, E_,
                                        (long)S_ * S_, (long)E_ * S_,
                                        (long)S_ * E_, 1.0f);
}